// round 4
// baseline (speedup 1.0000x reference)
#include <cuda_runtime.h>

#define TE 8       // node kernel tile
#define TEE 16     // edge kernel tile
#define NODES_MAX 50000

typedef unsigned long long ull;

__device__ float g_agg_s[(size_t)NODES_MAX * 64];
__device__ float g_agg_v[(size_t)NODES_MAX * 192];

__device__ __forceinline__ ull ffma2(ull a, ull b, ull c) {
  ull d;
  asm("fma.rn.f32x2 %0, %1, %2, %3;" : "=l"(d) : "l"(a), "l"(b), "l"(c));
  return d;
}
__device__ __forceinline__ ull pack2(float x) {
  ull d;
  asm("mov.b64 %0, {%1, %1};" : "=l"(d) : "f"(x));
  return d;
}
__device__ __forceinline__ void upk8(const ull* a, float* f) {
#pragma unroll
  for (int j = 0; j < 4; j++) {
    f[2 * j]     = __int_as_float((int)(unsigned)(a[j] & 0xffffffffull));
    f[2 * j + 1] = __int_as_float((int)(unsigned)(a[j] >> 32));
  }
}
__device__ __forceinline__ void upk16(const ull* a, float* f) {
#pragma unroll
  for (int j = 0; j < 8; j++) {
    f[2 * j]     = __int_as_float((int)(unsigned)(a[j] & 0xffffffffull));
    f[2 * j + 1] = __int_as_float((int)(unsigned)(a[j] >> 32));
  }
}
__device__ __forceinline__ float sigm(float x) { return 1.0f / (1.0f + __expf(-x)); }

#define RSQRT3 0.5773502692f
#define INV1   0.0622573010f   // 1/sqrt(258)
#define INV2   0.0883883476f   // 1/sqrt(128)
#define INV0   0.0625f         // 1/sqrt(256)
#define INVU   0.0883883476f   // 1/sqrt(128)

// ---- 8-edge accumulate (node kernel) ----
#define ACC4(arrRow, w2, A) do {                                               \
    ulonglong2 _r0 = *reinterpret_cast<const ulonglong2*>(arrRow);             \
    ulonglong2 _r1 = *reinterpret_cast<const ulonglong2*>((arrRow) + 4);       \
    (A)[0] = ffma2(_r0.x, (w2), (A)[0]);                                       \
    (A)[1] = ffma2(_r0.y, (w2), (A)[1]);                                       \
    (A)[2] = ffma2(_r1.x, (w2), (A)[2]);                                       \
    (A)[3] = ffma2(_r1.y, (w2), (A)[3]);                                       \
  } while (0)

// ---- 16-edge accumulate (edge kernel) ----
#define ACC8(arrRow, w2, A) do {                                               \
    ulonglong2 _r0 = *reinterpret_cast<const ulonglong2*>(arrRow);             \
    ulonglong2 _r1 = *reinterpret_cast<const ulonglong2*>((arrRow) + 4);       \
    ulonglong2 _r2 = *reinterpret_cast<const ulonglong2*>((arrRow) + 8);       \
    ulonglong2 _r3 = *reinterpret_cast<const ulonglong2*>((arrRow) + 12);      \
    (A)[0] = ffma2(_r0.x, (w2), (A)[0]);                                       \
    (A)[1] = ffma2(_r0.y, (w2), (A)[1]);                                       \
    (A)[2] = ffma2(_r1.x, (w2), (A)[2]);                                       \
    (A)[3] = ffma2(_r1.y, (w2), (A)[3]);                                       \
    (A)[4] = ffma2(_r2.x, (w2), (A)[4]);                                       \
    (A)[5] = ffma2(_r2.y, (w2), (A)[5]);                                       \
    (A)[6] = ffma2(_r3.x, (w2), (A)[6]);                                       \
    (A)[7] = ffma2(_r3.y, (w2), (A)[7]);                                       \
  } while (0)

// node-kernel (8-edge) GEMM helpers, MLP=8 weight batching
template <int K, int LDW, int RS>
__device__ __forceinline__ void gemmK(const float* __restrict__ W, int o,
                                      const float* __restrict__ row, ull* acc) {
#pragma unroll 1
  for (int k0 = 0; k0 < K; k0 += 8) {
    float w[8];
#pragma unroll
    for (int j = 0; j < 8; j++) w[j] = __ldg(W + (size_t)(k0 + j) * LDW + o);
#pragma unroll
    for (int j = 0; j < 8; j++) {
      ull w2 = pack2(w[j]);
      ACC4(row + (size_t)(k0 + j) * RS, w2, acc);
    }
  }
}
template <int K, int LDW, int RS>
__device__ __forceinline__ void gemmK2(const float* __restrict__ W, int o,
                                       const float* __restrict__ row0,
                                       const float* __restrict__ row1,
                                       ull* accA, ull* accB) {
#pragma unroll 1
  for (int k0 = 0; k0 < K; k0 += 8) {
    float w[8];
#pragma unroll
    for (int j = 0; j < 8; j++) w[j] = __ldg(W + (size_t)(k0 + j) * LDW + o);
#pragma unroll
    for (int j = 0; j < 8; j++) {
      ull w2 = pack2(w[j]);
      ACC4(row0 + (size_t)(k0 + j) * RS, w2, accA);
      ACC4(row1 + (size_t)(k0 + j) * RS, w2, accB);
    }
  }
}

// edge-kernel (16-edge) GEMM helpers
template <int K, int LDW, int RS>
__device__ __forceinline__ void gemm16(const float* __restrict__ W, int o,
                                       const float* __restrict__ row, ull* acc) {
#pragma unroll 1
  for (int k0 = 0; k0 < K; k0 += 8) {
    float w[8];
#pragma unroll
    for (int j = 0; j < 8; j++) w[j] = __ldg(W + (size_t)(k0 + j) * LDW + o);
#pragma unroll
    for (int j = 0; j < 8; j++) {
      ull w2 = pack2(w[j]);
      ACC8(row + (size_t)(k0 + j) * RS, w2, acc);
    }
  }
}
template <int K, int LDW, int RS>
__device__ __forceinline__ void gemm16x2(const float* __restrict__ W, int o,
                                         const float* __restrict__ row0,
                                         const float* __restrict__ row1,
                                         ull* accA, ull* accB) {
#pragma unroll 1
  for (int k0 = 0; k0 < K; k0 += 8) {
    float w[8];
#pragma unroll
    for (int j = 0; j < 8; j++) w[j] = __ldg(W + (size_t)(k0 + j) * LDW + o);
#pragma unroll
    for (int j = 0; j < 8; j++) {
      ull w2 = pack2(w[j]);
      ACC8(row0 + (size_t)(k0 + j) * RS, w2, accA);
      ACC8(row1 + (size_t)(k0 + j) * RS, w2, accB);
    }
  }
}

__global__ void zero_kernel(int N) {
  size_t i = (size_t)blockIdx.x * blockDim.x + threadIdx.x;
  size_t stride = (size_t)gridDim.x * blockDim.x;
  float4 z = make_float4(0.f, 0.f, 0.f, 0.f);
  size_t n_s = (size_t)N * 64 / 4;
  for (size_t t = i; t < n_s; t += stride) reinterpret_cast<float4*>(g_agg_s)[t] = z;
  size_t n_v = (size_t)N * 192 / 4;
  for (size_t t = i; t < n_v; t += stride) reinterpret_cast<float4*>(g_agg_v)[t] = z;
}

// ---------------------------------------------------------------------------
// Edge kernel: 16 edges/CTA, raw-only smem (a_s factored to epilogues).
// smem = 70.1 KB -> 3 CTAs/SM.
// ---------------------------------------------------------------------------
#define OFF_XS   0        // [130][16] raw xs
#define OFF_D1   2080     // [128][16]
#define OFF_XV   4128     // [128*3][16] raw xv
#define OFF_MS   10272    // [64][16]  silu output (raw)
#define OFF_G    11296    // [64][16]
#define OFF_D2   12320    // [64][16]
#define OFF_MV   13344    // [64*3][16] raw mv
#define OFF_P    16416    // [64][16]
#define OFF_ASX  17440
#define OFF_AVX  17456    // [3][16]
#define OFF_SND  17504
#define OFF_RCV  17520
#define EDGE_SMEM_FLOATS 17536
#define EDGE_SMEM_BYTES (EDGE_SMEM_FLOATS * 4)

__global__ void __launch_bounds__(128) edge_kernel(
    const float* __restrict__ node_s, const float* __restrict__ node_v,
    const float* __restrict__ eas, const float* __restrict__ eav,
    const float* __restrict__ add_feat,
    const float* __restrict__ Wss1, const float* __restrict__ Wvs1,
    const float* __restrict__ Wsv1, const float* __restrict__ Wvv1,
    const float* __restrict__ b1,
    const float* __restrict__ Wss2, const float* __restrict__ Wvs2,
    const float* __restrict__ Wsv2, const float* __restrict__ Wvv2,
    const float* __restrict__ b2,
    const int* __restrict__ senders, const int* __restrict__ receivers,
    int E)
{
  extern __shared__ __align__(16) float sm[];
  float* xs  = sm + OFF_XS;    // raw
  float* d1  = sm + OFF_D1;
  float* xv  = sm + OFF_XV;    // raw, [(v*3+c)][16]
  float* ms  = sm + OFF_MS;    // raw silu
  float* gT  = sm + OFF_G;
  float* d2  = sm + OFF_D2;
  float* mv  = sm + OFF_MV;    // raw gated vectors
  float* pT  = sm + OFF_P;
  float* asx = sm + OFF_ASX;
  float* avx = sm + OFF_AVX;
  int* sndx = (int*)(sm + OFF_SND);
  int* rcvx = (int*)(sm + OFF_RCV);

  const int tid = threadIdx.x;
  const int e0 = blockIdx.x * TEE;

  if (tid < TEE) {
    int ge = e0 + tid;
    bool val = ge < E;
    sndx[tid] = val ? senders[ge] : 0;
    rcvx[tid] = val ? receivers[ge] : -1;
    asx[tid]  = val ? eas[ge] : 0.f;
#pragma unroll
    for (int i = 0; i < 3; i++) avx[i * 16 + tid] = val ? eav[ge * 3 + i] : 0.f;
  }
  __syncthreads();

  // gather raw xs
  for (int idx = tid; idx < TEE * 130; idx += 128) {
    int e = idx / 130, s = idx - e * 130;
    int r = rcvx[e] < 0 ? 0 : rcvx[e];
    float v;
    if (s < 64)       v = __ldg(node_s + (size_t)sndx[e] * 64 + s);
    else if (s < 128) v = __ldg(node_s + (size_t)r * 64 + (s - 64));
    else {
      int ge = e0 + e;
      v = (ge < E) ? __ldg(add_feat + (size_t)ge * 2 + (s - 128)) : 0.f;
    }
    xs[s * 16 + e] = v;
  }
  // gather raw xv
  for (int idx = tid; idx < TEE * 384; idx += 128) {
    int e = idx / 384, j = idx - e * 384;
    int r = rcvx[e] < 0 ? 0 : rcvx[e];
    float v = (j < 192) ? __ldg(node_v + (size_t)sndx[e] * 192 + j)
                        : __ldg(node_v + (size_t)r * 192 + (j - 192));
    xv[j * 16 + e] = v;
  }
  __syncthreads();

  // d1 = (xv . av) / sqrt3   (raw xv, raw av)
  for (int t = tid; t < TEE * 128; t += 128) {
    int v = t >> 4, e = t & 15;
    d1[v * 16 + e] = (xv[(v * 3 + 0) * 16 + e] * avx[e] +
                      xv[(v * 3 + 1) * 16 + e] * avx[16 + e] +
                      xv[(v * 3 + 2) * 16 + e] * avx[32 + e]) * RSQRT3;
  }
  __syncthreads();

  // ---- m1 scalar: s1 = a_s*(xs@Wss1) + d1@Wvs1 ----
  {
    const int o = tid;
    ull accS[8] = {0,0,0,0,0,0,0,0}, accV[8] = {0,0,0,0,0,0,0,0};
    gemm16<128, 128, 16>(Wss1, o, xs, accS);
    {
      float w0 = __ldg(Wss1 + (size_t)128 * 128 + o);
      float w1 = __ldg(Wss1 + (size_t)129 * 128 + o);
      ACC8(xs + 128 * 16, pack2(w0), accS);
      ACC8(xs + 129 * 16, pack2(w1), accS);
    }
    gemm16<128, 128, 16>(Wvs1, o, d1, accV);
    float ss[16], vv[16];
    upk16(accS, ss); upk16(accV, vv);
    float bo = __ldg(b1 + o);
    if (o < 64) {
#pragma unroll
      for (int e = 0; e < TEE; e++) {
        float s1 = (asx[e] * ss[e] + vv[e]) * INV1 + bo;
        ms[o * 16 + e] = s1 * sigm(s1);
      }
    } else {
#pragma unroll
      for (int e = 0; e < TEE; e++) {
        float s1 = (asx[e] * ss[e] + vv[e]) * INV1 + bo;
        gT[(o - 64) * 16 + e] = sigm(s1);
      }
    }
  }
  __syncthreads();

  // ---- m1 vector: v[o,i] = (p[o]*av_i + a_s*q_i[o]) * g * INV1 ----
  {
    const int o = tid & 63;
    ull accA[8] = {0,0,0,0,0,0,0,0}, accB[8] = {0,0,0,0,0,0,0,0};
    if (tid < 64) {          // q0, q1 = raw xv @ Wvv1 (comps 0,1)
      gemm16x2<128, 64, 48>(Wvv1, o, xv + 0 * 16, xv + 1 * 16, accA, accB);
    } else {                 // q2 in accA; p = xs @ Wsv1 in accB
      gemm16<128, 64, 48>(Wvv1, o, xv + 2 * 16, accA);
      gemm16<128, 64, 16>(Wsv1, o, xs, accB);
      {
        float w0 = __ldg(Wsv1 + (size_t)128 * 64 + o);
        float w1 = __ldg(Wsv1 + (size_t)129 * 64 + o);
        ACC8(xs + 128 * 16, pack2(w0), accB);
        ACC8(xs + 129 * 16, pack2(w1), accB);
      }
      float pf[16]; upk16(accB, pf);
#pragma unroll
      for (int e = 0; e < TEE; e++) pT[o * 16 + e] = pf[e];
    }
    __syncthreads();
    float qa[16], qb[16];
    upk16(accA, qa); upk16(accB, qb);
    if (tid < 64) {
#pragma unroll
      for (int e = 0; e < TEE; e++) {
        float gi = gT[o * 16 + e] * INV1;
        float p = pT[o * 16 + e], a = asx[e];
        mv[(o * 3 + 0) * 16 + e] = (p * avx[e]      + a * qa[e]) * gi;
        mv[(o * 3 + 1) * 16 + e] = (p * avx[16 + e] + a * qb[e]) * gi;
      }
    } else {
#pragma unroll
      for (int e = 0; e < TEE; e++) {
        float gi = gT[o * 16 + e] * INV1;
        mv[(o * 3 + 2) * 16 + e] = (pT[o * 16 + e] * avx[32 + e] + asx[e] * qa[e]) * gi;
      }
    }
  }
  __syncthreads();

  // d2 = (mv . av)/sqrt3  (raw mv)
  for (int t = tid; t < TEE * 64; t += 128) {
    int v = t >> 4, e = t & 15;
    d2[v * 16 + e] = (mv[(v * 3 + 0) * 16 + e] * avx[e] +
                      mv[(v * 3 + 1) * 16 + e] * avx[16 + e] +
                      mv[(v * 3 + 2) * 16 + e] * avx[32 + e]) * RSQRT3;
  }
  __syncthreads();

  // ---- m2 scalar: s2 = a_s*(ms@Wss2) + d2@Wvs2 ; scatter silu part ----
  {
    const int o = tid;
    ull accS[8] = {0,0,0,0,0,0,0,0}, accV[8] = {0,0,0,0,0,0,0,0};
    gemm16<64, 128, 16>(Wss2, o, ms, accS);
    gemm16<64, 128, 16>(Wvs2, o, d2, accV);
    float ss[16], vv[16];
    upk16(accS, ss); upk16(accV, vv);
    float bo = __ldg(b2 + o);
    if (o < 64) {
#pragma unroll
      for (int e = 0; e < TEE; e++) {
        float s2 = (asx[e] * ss[e] + vv[e]) * INV2 + bo;
        float m = s2 * sigm(s2);
        int r = rcvx[e];
        if (r >= 0) atomicAdd(g_agg_s + (size_t)r * 64 + o, m);
      }
    } else {
#pragma unroll
      for (int e = 0; e < TEE; e++) {
        float s2 = (asx[e] * ss[e] + vv[e]) * INV2 + bo;
        gT[(o - 64) * 16 + e] = sigm(s2);
      }
    }
  }
  __syncthreads();

  // ---- m2 vector (+ atomic scatter) ----
  {
    const int o = tid & 63;
    ull accA[8] = {0,0,0,0,0,0,0,0}, accB[8] = {0,0,0,0,0,0,0,0};
    if (tid < 64) {
      gemm16x2<64, 64, 48>(Wvv2, o, mv + 0 * 16, mv + 1 * 16, accA, accB);
    } else {
      gemm16<64, 64, 48>(Wvv2, o, mv + 2 * 16, accA);
      gemm16<64, 64, 16>(Wsv2, o, ms, accB);
      float pf[16]; upk16(accB, pf);
#pragma unroll
      for (int e = 0; e < TEE; e++) pT[o * 16 + e] = pf[e];
    }
    __syncthreads();
    float qa[16], qb[16];
    upk16(accA, qa); upk16(accB, qb);
    if (tid < 64) {
#pragma unroll
      for (int e = 0; e < TEE; e++) {
        int r = rcvx[e];
        if (r < 0) continue;
        float gi = gT[o * 16 + e] * INV2;
        float p = pT[o * 16 + e], a = asx[e];
        atomicAdd(g_agg_v + (size_t)r * 192 + o * 3 + 0, (p * avx[e]      + a * qa[e]) * gi);
        atomicAdd(g_agg_v + (size_t)r * 192 + o * 3 + 1, (p * avx[16 + e] + a * qb[e]) * gi);
      }
    } else {
#pragma unroll
      for (int e = 0; e < TEE; e++) {
        int r = rcvx[e];
        if (r < 0) continue;
        float gi = gT[o * 16 + e] * INV2;
        atomicAdd(g_agg_v + (size_t)r * 192 + o * 3 + 2,
                  (pT[o * 16 + e] * avx[32 + e] + asx[e] * qa[e]) * gi);
      }
    }
  }
}

// ---------------------------------------------------------------------------
// Node kernel (unchanged from R3): TE=8, static smem
// ---------------------------------------------------------------------------
__global__ void __launch_bounds__(128, 5) node_kernel(
    const float* __restrict__ node_s, const float* __restrict__ node_v,
    const float* __restrict__ nas, const float* __restrict__ nav,
    const float* __restrict__ Wss0, const float* __restrict__ Wvs0,
    const float* __restrict__ Wsv0, const float* __restrict__ Wvv0,
    const float* __restrict__ b0,
    const float* __restrict__ Wssu, const float* __restrict__ Wvsu,
    const float* __restrict__ Wsvu, const float* __restrict__ Wvvu,
    const float* __restrict__ bu,
    float* __restrict__ out, int N)
{
  __shared__ __align__(16) float xs_rT[128][TE];
  __shared__ __align__(16) float xs_aT[128][TE];
  __shared__ __align__(16) float d1T[128][TE];
  __shared__ __align__(16) float xvaT[128][3][TE];
  __shared__ __align__(16) float hs_rT[64][TE];
  __shared__ __align__(16) float hs_aT[64][TE];
  __shared__ __align__(16) float gT[64][TE];
  __shared__ __align__(16) float d2T[64][TE];
  __shared__ __align__(16) float hvaT[64][3][TE];
  __shared__ __align__(16) float pT[64][TE];
  __shared__ float asx[TE], avx[3][TE];

  const int tid = threadIdx.x;
  const int n0 = blockIdx.x * TE;

  if (tid < TE) {
    int n = n0 + tid;
    bool val = n < N;
    asx[tid] = val ? nas[n] : 0.f;
#pragma unroll
    for (int i = 0; i < 3; i++) avx[i][tid] = val ? nav[n * 3 + i] : 0.f;
  }
  __syncthreads();

  for (int idx = tid; idx < TE * 128; idx += 128) {
    int e = idx >> 7, s = idx & 127;
    int n = n0 + e; if (n >= N) n = 0;
    float v = (s < 64) ? __ldg(node_s + (size_t)n * 64 + s)
                       : g_agg_s[(size_t)n * 64 + (s - 64)];
    xs_rT[s][e] = v;
    xs_aT[s][e] = v * asx[e];
  }
  for (int idx = tid; idx < TE * 384; idx += 128) {
    int e = idx / 384, j = idx - e * 384;
    int n = n0 + e; if (n >= N) n = 0;
    float v = (j < 192) ? __ldg(node_v + (size_t)n * 192 + j)
                        : g_agg_v[(size_t)n * 192 + (j - 192)];
    xvaT[j / 3][j % 3][e] = v;
  }
  __syncthreads();

  for (int t = tid; t < TE * 128; t += 128) {
    int v = t >> 3, e = t & 7;
    float r0 = xvaT[v][0][e], r1 = xvaT[v][1][e], r2 = xvaT[v][2][e];
    d1T[v][e] = (r0 * avx[0][e] + r1 * avx[1][e] + r2 * avx[2][e]) * RSQRT3;
    float a = asx[e];
    xvaT[v][0][e] = r0 * a; xvaT[v][1][e] = r1 * a; xvaT[v][2][e] = r2 * a;
  }
  __syncthreads();

  // ---- u0 scalar ----
  {
    const int o = tid;
    ull acc[4] = {0, 0, 0, 0};
    gemmK<128, 128, TE>(Wss0, o, &xs_aT[0][0], acc);
    gemmK<128, 128, TE>(Wvs0, o, &d1T[0][0], acc);
    float sv[8]; upk8(acc, sv);
    float bo = __ldg(b0 + o);
    if (o < 64) {
#pragma unroll
      for (int e = 0; e < TE; e++) {
        float s1 = sv[e] * INV0 + bo;
        float m = s1 * sigm(s1);
        hs_rT[o][e] = m;
        hs_aT[o][e] = m * asx[e];
      }
    } else {
#pragma unroll
      for (int e = 0; e < TE; e++) {
        gT[o - 64][e] = sigm(sv[e] * INV0 + bo);
      }
    }
  }
  __syncthreads();

  // ---- u0 vector ----
  {
    const int o = tid & 63;
    ull accA[4] = {0, 0, 0, 0}, accB[4] = {0, 0, 0, 0};
    if (tid < 64) {
      gemmK2<128, 64, 3 * TE>(Wvv0, o, &xvaT[0][0][0], &xvaT[0][1][0], accA, accB);
    } else {
      gemmK<128, 64, 3 * TE>(Wvv0, o, &xvaT[0][2][0], accA);
      gemmK<128, 64, TE>(Wsv0, o, &xs_rT[0][0], accB);
      float pf[8]; upk8(accB, pf);
#pragma unroll
      for (int e = 0; e < TE; e++) pT[o][e] = pf[e];
    }
    __syncthreads();
    float qa[8], qb[8];
    upk8(accA, qa); upk8(accB, qb);
    if (tid < 64) {
#pragma unroll
      for (int e = 0; e < TE; e++) {
        float gi = gT[o][e] * INV0;
        float p = pT[o][e];
        hvaT[o][0][e] = (qa[e] + p * avx[0][e]) * gi;
        hvaT[o][1][e] = (qb[e] + p * avx[1][e]) * gi;
      }
    } else {
#pragma unroll
      for (int e = 0; e < TE; e++) {
        float gi = gT[o][e] * INV0;
        hvaT[o][2][e] = (qa[e] + qb[e] * avx[2][e]) * gi;
      }
    }
  }
  __syncthreads();

  for (int t = tid; t < TE * 64; t += 128) {
    int v = t >> 3, e = t & 7;
    float r0 = hvaT[v][0][e], r1 = hvaT[v][1][e], r2 = hvaT[v][2][e];
    d2T[v][e] = (r0 * avx[0][e] + r1 * avx[1][e] + r2 * avx[2][e]) * RSQRT3;
    float a = asx[e];
    hvaT[v][0][e] = r0 * a; hvaT[v][1][e] = r1 * a; hvaT[v][2][e] = r2 * a;
  }
  __syncthreads();

  // ---- u1 scalar + residual ----
  if (tid < 64) {
    const int o = tid;
    ull acc[4] = {0, 0, 0, 0};
    gemmK<64, 64, TE>(Wssu, o, &hs_aT[0][0], acc);
    gemmK<64, 64, TE>(Wvsu, o, &d2T[0][0], acc);
    float sv[8]; upk8(acc, sv);
    float bo = __ldg(bu + o);
#pragma unroll
    for (int e = 0; e < TE; e++) {
      int n = n0 + e;
      if (n < N)
        out[(size_t)n * 256 + o] =
            __ldg(node_s + (size_t)n * 64 + o) + sv[e] * INVU + bo;
    }
  }

  // ---- u1 vector + residual ----
  {
    const int o = tid & 63;
    ull accA[4] = {0, 0, 0, 0}, accB[4] = {0, 0, 0, 0};
    if (tid < 64) {
      gemmK2<64, 64, 3 * TE>(Wvvu, o, &hvaT[0][0][0], &hvaT[0][1][0], accA, accB);
    } else {
      gemmK<64, 64, 3 * TE>(Wvvu, o, &hvaT[0][2][0], accA);
      gemmK<64, 64, TE>(Wsvu, o, &hs_rT[0][0], accB);
      float pf[8]; upk8(accB, pf);
#pragma unroll
      for (int e = 0; e < TE; e++) pT[o][e] = pf[e];
    }
    __syncthreads();
    float qa[8], qb[8];
    upk8(accA, qa); upk8(accB, qb);
    if (tid < 64) {
#pragma unroll
      for (int e = 0; e < TE; e++) {
        int n = n0 + e;
        if (n >= N) continue;
        float p = pT[o][e];
        out[(size_t)n * 256 + 64 + o * 3 + 0] =
            __ldg(node_v + (size_t)n * 192 + o * 3 + 0) + (qa[e] + p * avx[0][e]) * INVU;
        out[(size_t)n * 256 + 64 + o * 3 + 1] =
            __ldg(node_v + (size_t)n * 192 + o * 3 + 1) + (qb[e] + p * avx[1][e]) * INVU;
      }
    } else {
#pragma unroll
      for (int e = 0; e < TE; e++) {
        int n = n0 + e;
        if (n >= N) continue;
        out[(size_t)n * 256 + 64 + o * 3 + 2] =
            __ldg(node_v + (size_t)n * 192 + o * 3 + 2) + (qa[e] + qb[e] * avx[2][e]) * INVU;
      }
    }
  }
}

extern "C" void kernel_launch(void* const* d_in, const int* in_sizes, int n_in,
                              void* d_out, int out_size) {
  const float* node_s = (const float*)d_in[0];
  const float* node_v = (const float*)d_in[1];
  const float* nas    = (const float*)d_in[2];
  const float* nav    = (const float*)d_in[3];
  const float* eas    = (const float*)d_in[4];
  const float* eav    = (const float*)d_in[5];
  const float* add_f  = (const float*)d_in[6];
  const float* m1Wss  = (const float*)d_in[7];
  const float* m1Wvs  = (const float*)d_in[8];
  const float* m1Wsv  = (const float*)d_in[9];
  const float* m1Wvv  = (const float*)d_in[10];
  const float* m1b    = (const float*)d_in[11];
  const float* m2Wss  = (const float*)d_in[12];
  const float* m2Wvs  = (const float*)d_in[13];
  const float* m2Wsv  = (const float*)d_in[14];
  const float* m2Wvv  = (const float*)d_in[15];
  const float* m2b    = (const float*)d_in[16];
  const float* u0Wss  = (const float*)d_in[17];
  const float* u0Wvs  = (const float*)d_in[18];
  const float* u0Wsv  = (const float*)d_in[19];
  const float* u0Wvv  = (const float*)d_in[20];
  const float* u0b    = (const float*)d_in[21];
  const float* u1Wss  = (const float*)d_in[22];
  const float* u1Wvs  = (const float*)d_in[23];
  const float* u1Wsv  = (const float*)d_in[24];
  const float* u1Wvv  = (const float*)d_in[25];
  const float* u1b    = (const float*)d_in[26];
  const int* senders   = (const int*)d_in[27];
  const int* receivers = (const int*)d_in[28];

  int E = in_sizes[27];
  int N = in_sizes[0] / 64;

  cudaFuncSetAttribute(edge_kernel, cudaFuncAttributeMaxDynamicSharedMemorySize,
                       EDGE_SMEM_BYTES);

  zero_kernel<<<512, 256>>>(N);
  edge_kernel<<<(E + TEE - 1) / TEE, 128, EDGE_SMEM_BYTES>>>(
      node_s, node_v, eas, eav, add_f,
      m1Wss, m1Wvs, m1Wsv, m1Wvv, m1b,
      m2Wss, m2Wvs, m2Wsv, m2Wvv, m2b,
      senders, receivers, E);
  node_kernel<<<(N + TE - 1) / TE, 128>>>(
      node_s, node_v, nas, nav,
      u0Wss, u0Wvs, u0Wsv, u0Wvv, u0b,
      u1Wss, u1Wvs, u1Wsv, u1Wvv, u1b,
      (float*)d_out, N);
}

// round 5
// speedup vs baseline: 1.1183x; 1.1183x over previous
#include <cuda_runtime.h>

#define TE 8       // node kernel tile
#define TEE 16     // edge kernel tile
#define NT 256     // edge kernel threads
#define NODES_MAX 50000

typedef unsigned long long ull;

__device__ float g_agg_s[(size_t)NODES_MAX * 64];
__device__ float g_agg_v[(size_t)NODES_MAX * 192];

__device__ __forceinline__ ull ffma2(ull a, ull b, ull c) {
  ull d;
  asm("fma.rn.f32x2 %0, %1, %2, %3;" : "=l"(d) : "l"(a), "l"(b), "l"(c));
  return d;
}
__device__ __forceinline__ ull pack2(float x) {
  ull d;
  asm("mov.b64 %0, {%1, %1};" : "=l"(d) : "f"(x));
  return d;
}
__device__ __forceinline__ void upk8(const ull* a, float* f) {
#pragma unroll
  for (int j = 0; j < 4; j++) {
    f[2 * j]     = __int_as_float((int)(unsigned)(a[j] & 0xffffffffull));
    f[2 * j + 1] = __int_as_float((int)(unsigned)(a[j] >> 32));
  }
}
__device__ __forceinline__ void upk16(const ull* a, float* f) {
#pragma unroll
  for (int j = 0; j < 8; j++) {
    f[2 * j]     = __int_as_float((int)(unsigned)(a[j] & 0xffffffffull));
    f[2 * j + 1] = __int_as_float((int)(unsigned)(a[j] >> 32));
  }
}
__device__ __forceinline__ float sigm(float x) { return 1.0f / (1.0f + __expf(-x)); }

#define RSQRT3 0.5773502692f
#define INV1   0.0622573010f   // 1/sqrt(258)
#define INV2   0.0883883476f   // 1/sqrt(128)
#define INV0   0.0625f         // 1/sqrt(256)
#define INVU   0.0883883476f   // 1/sqrt(128)

#define ACC4(arrRow, w2, A) do {                                               \
    ulonglong2 _r0 = *reinterpret_cast<const ulonglong2*>(arrRow);             \
    ulonglong2 _r1 = *reinterpret_cast<const ulonglong2*>((arrRow) + 4);       \
    (A)[0] = ffma2(_r0.x, (w2), (A)[0]);                                       \
    (A)[1] = ffma2(_r0.y, (w2), (A)[1]);                                       \
    (A)[2] = ffma2(_r1.x, (w2), (A)[2]);                                       \
    (A)[3] = ffma2(_r1.y, (w2), (A)[3]);                                       \
  } while (0)

#define ACC8(arrRow, w2, A) do {                                               \
    ulonglong2 _r0 = *reinterpret_cast<const ulonglong2*>(arrRow);             \
    ulonglong2 _r1 = *reinterpret_cast<const ulonglong2*>((arrRow) + 4);       \
    ulonglong2 _r2 = *reinterpret_cast<const ulonglong2*>((arrRow) + 8);       \
    ulonglong2 _r3 = *reinterpret_cast<const ulonglong2*>((arrRow) + 12);      \
    (A)[0] = ffma2(_r0.x, (w2), (A)[0]);                                       \
    (A)[1] = ffma2(_r0.y, (w2), (A)[1]);                                       \
    (A)[2] = ffma2(_r1.x, (w2), (A)[2]);                                       \
    (A)[3] = ffma2(_r1.y, (w2), (A)[3]);                                       \
    (A)[4] = ffma2(_r2.x, (w2), (A)[4]);                                       \
    (A)[5] = ffma2(_r2.y, (w2), (A)[5]);                                       \
    (A)[6] = ffma2(_r3.x, (w2), (A)[6]);                                       \
    (A)[7] = ffma2(_r3.y, (w2), (A)[7]);                                       \
  } while (0)

// node-kernel (8-edge) helpers
template <int K, int LDW, int RS>
__device__ __forceinline__ void gemmK(const float* __restrict__ W, int o,
                                      const float* __restrict__ row, ull* acc) {
#pragma unroll 1
  for (int k0 = 0; k0 < K; k0 += 8) {
    float w[8];
#pragma unroll
    for (int j = 0; j < 8; j++) w[j] = __ldg(W + (size_t)(k0 + j) * LDW + o);
#pragma unroll
    for (int j = 0; j < 8; j++) {
      ull w2 = pack2(w[j]);
      ACC4(row + (size_t)(k0 + j) * RS, w2, acc);
    }
  }
}
template <int K, int LDW, int RS>
__device__ __forceinline__ void gemmK2(const float* __restrict__ W, int o,
                                       const float* __restrict__ row0,
                                       const float* __restrict__ row1,
                                       ull* accA, ull* accB) {
#pragma unroll 1
  for (int k0 = 0; k0 < K; k0 += 8) {
    float w[8];
#pragma unroll
    for (int j = 0; j < 8; j++) w[j] = __ldg(W + (size_t)(k0 + j) * LDW + o);
#pragma unroll
    for (int j = 0; j < 8; j++) {
      ull w2 = pack2(w[j]);
      ACC4(row0 + (size_t)(k0 + j) * RS, w2, accA);
      ACC4(row1 + (size_t)(k0 + j) * RS, w2, accB);
    }
  }
}

// edge-kernel (16-edge) helper, MLP=8 weight batching
template <int K, int LDW, int RS>
__device__ __forceinline__ void gemm16(const float* __restrict__ W, int o,
                                       const float* __restrict__ row, ull* acc) {
#pragma unroll 1
  for (int k0 = 0; k0 < K; k0 += 8) {
    float w[8];
#pragma unroll
    for (int j = 0; j < 8; j++) w[j] = __ldg(W + (size_t)(k0 + j) * LDW + o);
#pragma unroll
    for (int j = 0; j < 8; j++) {
      ull w2 = pack2(w[j]);
      ACC8(row + (size_t)(k0 + j) * RS, w2, acc);
    }
  }
}

__global__ void zero_kernel(int N) {
  size_t i = (size_t)blockIdx.x * blockDim.x + threadIdx.x;
  size_t stride = (size_t)gridDim.x * blockDim.x;
  float4 z = make_float4(0.f, 0.f, 0.f, 0.f);
  size_t n_s = (size_t)N * 64 / 4;
  for (size_t t = i; t < n_s; t += stride) reinterpret_cast<float4*>(g_agg_s)[t] = z;
  size_t n_v = (size_t)N * 192 / 4;
  for (size_t t = i; t < n_v; t += stride) reinterpret_cast<float4*>(g_agg_v)[t] = z;
}

// ---------------------------------------------------------------------------
// Edge kernel: 16 edges/CTA, 256 threads, split-GEMM roles, 3 CTAs/SM.
// ---------------------------------------------------------------------------
#define OFF_XS   0        // [130][16] raw xs
#define OFF_D1   2080     // [128][16] d1; later reused as partial-sum exchange
#define OFF_XV   4128     // [128*3][16] raw xv
#define OFF_MS   10272    // [64][16]
#define OFF_G    11296    // [64][16]
#define OFF_D2   12320    // [64][16]
#define OFF_MV   13344    // [64*3][16]
#define OFF_P    16416    // [64][16]
#define OFF_ASX  17440
#define OFF_AVX  17456    // [3][16]
#define OFF_SND  17504
#define OFF_RCV  17520
#define EDGE_SMEM_FLOATS 17536
#define EDGE_SMEM_BYTES (EDGE_SMEM_FLOATS * 4)

__global__ void __launch_bounds__(NT) edge_kernel(
    const float* __restrict__ node_s, const float* __restrict__ node_v,
    const float* __restrict__ eas, const float* __restrict__ eav,
    const float* __restrict__ add_feat,
    const float* __restrict__ Wss1, const float* __restrict__ Wvs1,
    const float* __restrict__ Wsv1, const float* __restrict__ Wvv1,
    const float* __restrict__ b1,
    const float* __restrict__ Wss2, const float* __restrict__ Wvs2,
    const float* __restrict__ Wsv2, const float* __restrict__ Wvv2,
    const float* __restrict__ b2,
    const int* __restrict__ senders, const int* __restrict__ receivers,
    int E)
{
  extern __shared__ __align__(16) float sm[];
  float* xs  = sm + OFF_XS;
  float* d1  = sm + OFF_D1;    // doubles as partial-sum exchange buffer
  float* xv  = sm + OFF_XV;
  float* ms  = sm + OFF_MS;
  float* gT  = sm + OFF_G;
  float* d2  = sm + OFF_D2;
  float* mv  = sm + OFF_MV;
  float* pT  = sm + OFF_P;
  float* asx = sm + OFF_ASX;
  float* avx = sm + OFF_AVX;
  int* sndx = (int*)(sm + OFF_SND);
  int* rcvx = (int*)(sm + OFF_RCV);

  const int tid = threadIdx.x;
  const int grp = tid >> 7;     // 0: scalar-S / q0 / q1 side, 1: scalar-V / q2 / p
  const int wg  = tid & 127;
  const int e0 = blockIdx.x * TEE;

  // S0: per-edge heads
  if (tid < TEE) {
    int ge = e0 + tid;
    bool val = ge < E;
    sndx[tid] = val ? senders[ge] : 0;
    rcvx[tid] = val ? receivers[ge] : -1;
    asx[tid]  = val ? eas[ge] : 0.f;
#pragma unroll
    for (int i = 0; i < 3; i++) avx[i * 16 + tid] = val ? eav[ge * 3 + i] : 0.f;
  }
  __syncthreads();

  // S1: gathers (raw)
  for (int idx = tid; idx < TEE * 130; idx += NT) {
    int e = idx / 130, s = idx - e * 130;
    int r = rcvx[e] < 0 ? 0 : rcvx[e];
    float v;
    if (s < 64)       v = __ldg(node_s + (size_t)sndx[e] * 64 + s);
    else if (s < 128) v = __ldg(node_s + (size_t)r * 64 + (s - 64));
    else {
      int ge = e0 + e;
      v = (ge < E) ? __ldg(add_feat + (size_t)ge * 2 + (s - 128)) : 0.f;
    }
    xs[s * 16 + e] = v;
  }
  for (int idx = tid; idx < TEE * 384; idx += NT) {
    int e = idx / 384, j = idx - e * 384;
    int r = rcvx[e] < 0 ? 0 : rcvx[e];
    float v = (j < 192) ? __ldg(node_v + (size_t)sndx[e] * 192 + j)
                        : __ldg(node_v + (size_t)r * 192 + (j - 192));
    xv[j * 16 + e] = v;
  }
  __syncthreads();

  // S2: d1 = (xv . av)/sqrt3
  for (int t = tid; t < TEE * 128; t += NT) {
    int v = t >> 4, e = t & 15;
    d1[v * 16 + e] = (xv[(v * 3 + 0) * 16 + e] * avx[e] +
                      xv[(v * 3 + 1) * 16 + e] * avx[16 + e] +
                      xv[(v * 3 + 2) * 16 + e] * avx[32 + e]) * RSQRT3;
  }
  __syncthreads();

  // S3: m1 scalar split GEMM (grp0: xs@Wss1; grp1: d1@Wvs1 -> exchange)
  float s1v[16];
  {
    ull acc[8] = {0,0,0,0,0,0,0,0};
    if (grp == 0) {
      gemm16<128, 128, 16>(Wss1, wg, xs, acc);
      float w0 = __ldg(Wss1 + (size_t)128 * 128 + wg);
      float w1 = __ldg(Wss1 + (size_t)129 * 128 + wg);
      ACC8(xs + 128 * 16, pack2(w0), acc);
      ACC8(xs + 129 * 16, pack2(w1), acc);
      upk16(acc, s1v);       // raw SS partial (a_s applied later)
    } else {
      gemm16<128, 128, 16>(Wvs1, wg, d1, acc);
      float vvf[16]; upk16(acc, vvf);
      asm volatile("bar.sync 1, 128;" ::: "memory");  // all grp1 d1-reads done
#pragma unroll
      for (int e = 0; e < TEE; e++) d1[wg * 16 + e] = vvf[e];
    }
  }
  __syncthreads();

  // S4: grp0 scalar epilogue, then all threads run m1 vector GEMM roles
  if (grp == 0) {
    float bo = __ldg(b1 + wg);
    if (wg < 64) {
#pragma unroll
      for (int e = 0; e < TEE; e++) {
        float s1 = (asx[e] * s1v[e] + d1[wg * 16 + e]) * INV1 + bo;
        ms[wg * 16 + e] = s1 * sigm(s1);
      }
    } else {
#pragma unroll
      for (int e = 0; e < TEE; e++) {
        float s1 = (asx[e] * s1v[e] + d1[wg * 16 + e]) * INV1 + bo;
        gT[(wg - 64) * 16 + e] = sigm(s1);
      }
    }
  }
  {
    const int o = tid & 63;
    const int role = tid >> 6;   // 0,1,2 = q components; 3 = p
    ull acc[8] = {0,0,0,0,0,0,0,0};
    if (role < 3) {
      gemm16<128, 64, 48>(Wvv1, o, xv + role * 16, acc);
    } else {
      gemm16<128, 64, 16>(Wsv1, o, xs, acc);
      float w0 = __ldg(Wsv1 + (size_t)128 * 64 + o);
      float w1 = __ldg(Wsv1 + (size_t)129 * 64 + o);
      ACC8(xs + 128 * 16, pack2(w0), acc);
      ACC8(xs + 129 * 16, pack2(w1), acc);
    }
    float q[16]; upk16(acc, q);
    if (role == 3) {
#pragma unroll
      for (int e = 0; e < TEE; e++) pT[o * 16 + e] = q[e];
    }
    __syncthreads();
    // S5: vector epilogue
    if (role < 3) {
#pragma unroll
      for (int e = 0; e < TEE; e++) {
        float gi = gT[o * 16 + e] * INV1;
        mv[(o * 3 + role) * 16 + e] =
            (pT[o * 16 + e] * avx[role * 16 + e] + asx[e] * q[e]) * gi;
      }
    }
  }
  __syncthreads();

  // S6: d2
  for (int t = tid; t < TEE * 64; t += NT) {
    int v = t >> 4, e = t & 15;
    d2[v * 16 + e] = (mv[(v * 3 + 0) * 16 + e] * avx[e] +
                      mv[(v * 3 + 1) * 16 + e] * avx[16 + e] +
                      mv[(v * 3 + 2) * 16 + e] * avx[32 + e]) * RSQRT3;
  }
  __syncthreads();

  // S7: m2 scalar split GEMM
  float s2v[16];
  {
    ull acc[8] = {0,0,0,0,0,0,0,0};
    if (grp == 0) {
      gemm16<64, 128, 16>(Wss2, wg, ms, acc);
      upk16(acc, s2v);
    } else {
      gemm16<64, 128, 16>(Wvs2, wg, d2, acc);
      float vvf[16]; upk16(acc, vvf);
      // d1 space is idle (its last readers were in S4, two barriers ago)
#pragma unroll
      for (int e = 0; e < TEE; e++) d1[wg * 16 + e] = vvf[e];
    }
  }
  __syncthreads();

  // S8: grp0 scalar epilogue (atomics + gates), then m2 vector GEMM roles
  if (grp == 0) {
    float bo = __ldg(b2 + wg);
    if (wg < 64) {
#pragma unroll
      for (int e = 0; e < TEE; e++) {
        float s2 = (asx[e] * s2v[e] + d1[wg * 16 + e]) * INV2 + bo;
        float m = s2 * sigm(s2);
        int r = rcvx[e];
        if (r >= 0) atomicAdd(g_agg_s + (size_t)r * 64 + wg, m);
      }
    } else {
#pragma unroll
      for (int e = 0; e < TEE; e++) {
        float s2 = (asx[e] * s2v[e] + d1[wg * 16 + e]) * INV2 + bo;
        gT[(wg - 64) * 16 + e] = sigm(s2);
      }
    }
  }
  {
    const int o = tid & 63;
    const int role = tid >> 6;
    ull acc[8] = {0,0,0,0,0,0,0,0};
    if (role < 3) {
      gemm16<64, 64, 48>(Wvv2, o, mv + role * 16, acc);
    } else {
      gemm16<64, 64, 16>(Wsv2, o, ms, acc);
    }
    float q[16]; upk16(acc, q);
    if (role == 3) {
#pragma unroll
      for (int e = 0; e < TEE; e++) pT[o * 16 + e] = q[e];
    }
    __syncthreads();
    // S9: vector scatter
    if (role < 3) {
#pragma unroll
      for (int e = 0; e < TEE; e++) {
        int r = rcvx[e];
        if (r < 0) continue;
        float gi = gT[o * 16 + e] * INV2;
        atomicAdd(g_agg_v + (size_t)r * 192 + o * 3 + role,
                  (pT[o * 16 + e] * avx[role * 16 + e] + asx[e] * q[e]) * gi);
      }
    }
  }
}

// ---------------------------------------------------------------------------
// Node kernel (unchanged from R3 winner): TE=8, 128 threads, static smem
// ---------------------------------------------------------------------------
__global__ void __launch_bounds__(128, 5) node_kernel(
    const float* __restrict__ node_s, const float* __restrict__ node_v,
    const float* __restrict__ nas, const float* __restrict__ nav,
    const float* __restrict__ Wss0, const float* __restrict__ Wvs0,
    const float* __restrict__ Wsv0, const float* __restrict__ Wvv0,
    const float* __restrict__ b0,
    const float* __restrict__ Wssu, const float* __restrict__ Wvsu,
    const float* __restrict__ Wsvu, const float* __restrict__ Wvvu,
    const float* __restrict__ bu,
    float* __restrict__ out, int N)
{
  __shared__ __align__(16) float xs_rT[128][TE];
  __shared__ __align__(16) float xs_aT[128][TE];
  __shared__ __align__(16) float d1T[128][TE];
  __shared__ __align__(16) float xvaT[128][3][TE];
  __shared__ __align__(16) float hs_rT[64][TE];
  __shared__ __align__(16) float hs_aT[64][TE];
  __shared__ __align__(16) float gT[64][TE];
  __shared__ __align__(16) float d2T[64][TE];
  __shared__ __align__(16) float hvaT[64][3][TE];
  __shared__ __align__(16) float pT[64][TE];
  __shared__ float asx[TE], avx[3][TE];

  const int tid = threadIdx.x;
  const int n0 = blockIdx.x * TE;

  if (tid < TE) {
    int n = n0 + tid;
    bool val = n < N;
    asx[tid] = val ? nas[n] : 0.f;
#pragma unroll
    for (int i = 0; i < 3; i++) avx[i][tid] = val ? nav[n * 3 + i] : 0.f;
  }
  __syncthreads();

  for (int idx = tid; idx < TE * 128; idx += 128) {
    int e = idx >> 7, s = idx & 127;
    int n = n0 + e; if (n >= N) n = 0;
    float v = (s < 64) ? __ldg(node_s + (size_t)n * 64 + s)
                       : g_agg_s[(size_t)n * 64 + (s - 64)];
    xs_rT[s][e] = v;
    xs_aT[s][e] = v * asx[e];
  }
  for (int idx = tid; idx < TE * 384; idx += 128) {
    int e = idx / 384, j = idx - e * 384;
    int n = n0 + e; if (n >= N) n = 0;
    float v = (j < 192) ? __ldg(node_v + (size_t)n * 192 + j)
                        : g_agg_v[(size_t)n * 192 + (j - 192)];
    xvaT[j / 3][j % 3][e] = v;
  }
  __syncthreads();

  for (int t = tid; t < TE * 128; t += 128) {
    int v = t >> 3, e = t & 7;
    float r0 = xvaT[v][0][e], r1 = xvaT[v][1][e], r2 = xvaT[v][2][e];
    d1T[v][e] = (r0 * avx[0][e] + r1 * avx[1][e] + r2 * avx[2][e]) * RSQRT3;
    float a = asx[e];
    xvaT[v][0][e] = r0 * a; xvaT[v][1][e] = r1 * a; xvaT[v][2][e] = r2 * a;
  }
  __syncthreads();

  // ---- u0 scalar ----
  {
    const int o = tid;
    ull acc[4] = {0, 0, 0, 0};
    gemmK<128, 128, TE>(Wss0, o, &xs_aT[0][0], acc);
    gemmK<128, 128, TE>(Wvs0, o, &d1T[0][0], acc);
    float sv[8]; upk8(acc, sv);
    float bo = __ldg(b0 + o);
    if (o < 64) {
#pragma unroll
      for (int e = 0; e < TE; e++) {
        float s1 = sv[e] * INV0 + bo;
        float m = s1 * sigm(s1);
        hs_rT[o][e] = m;
        hs_aT[o][e] = m * asx[e];
      }
    } else {
#pragma unroll
      for (int e = 0; e < TE; e++) {
        gT[o - 64][e] = sigm(sv[e] * INV0 + bo);
      }
    }
  }
  __syncthreads();

  // ---- u0 vector ----
  {
    const int o = tid & 63;
    ull accA[4] = {0, 0, 0, 0}, accB[4] = {0, 0, 0, 0};
    if (tid < 64) {
      gemmK2<128, 64, 3 * TE>(Wvv0, o, &xvaT[0][0][0], &xvaT[0][1][0], accA, accB);
    } else {
      gemmK<128, 64, 3 * TE>(Wvv0, o, &xvaT[0][2][0], accA);
      gemmK<128, 64, TE>(Wsv0, o, &xs_rT[0][0], accB);
      float pf[8]; upk8(accB, pf);
#pragma unroll
      for (int e = 0; e < TE; e++) pT[o][e] = pf[e];
    }
    __syncthreads();
    float qa[8], qb[8];
    upk8(accA, qa); upk8(accB, qb);
    if (tid < 64) {
#pragma unroll
      for (int e = 0; e < TE; e++) {
        float gi = gT[o][e] * INV0;
        float p = pT[o][e];
        hvaT[o][0][e] = (qa[e] + p * avx[0][e]) * gi;
        hvaT[o][1][e] = (qb[e] + p * avx[1][e]) * gi;
      }
    } else {
#pragma unroll
      for (int e = 0; e < TE; e++) {
        float gi = gT[o][e] * INV0;
        hvaT[o][2][e] = (qa[e] + qb[e] * avx[2][e]) * gi;
      }
    }
  }
  __syncthreads();

  for (int t = tid; t < TE * 64; t += 128) {
    int v = t >> 3, e = t & 7;
    float r0 = hvaT[v][0][e], r1 = hvaT[v][1][e], r2 = hvaT[v][2][e];
    d2T[v][e] = (r0 * avx[0][e] + r1 * avx[1][e] + r2 * avx[2][e]) * RSQRT3;
    float a = asx[e];
    hvaT[v][0][e] = r0 * a; hvaT[v][1][e] = r1 * a; hvaT[v][2][e] = r2 * a;
  }
  __syncthreads();

  // ---- u1 scalar + residual ----
  if (tid < 64) {
    const int o = tid;
    ull acc[4] = {0, 0, 0, 0};
    gemmK<64, 64, TE>(Wssu, o, &hs_aT[0][0], acc);
    gemmK<64, 64, TE>(Wvsu, o, &d2T[0][0], acc);
    float sv[8]; upk8(acc, sv);
    float bo = __ldg(bu + o);
#pragma unroll
    for (int e = 0; e < TE; e++) {
      int n = n0 + e;
      if (n < N)
        out[(size_t)n * 256 + o] =
            __ldg(node_s + (size_t)n * 64 + o) + sv[e] * INVU + bo;
    }
  }

  // ---- u1 vector + residual ----
  {
    const int o = tid & 63;
    ull accA[4] = {0, 0, 0, 0}, accB[4] = {0, 0, 0, 0};
    if (tid < 64) {
      gemmK2<64, 64, 3 * TE>(Wvvu, o, &hvaT[0][0][0], &hvaT[0][1][0], accA, accB);
    } else {
      gemmK<64, 64, 3 * TE>(Wvvu, o, &hvaT[0][2][0], accA);
      gemmK<64, 64, TE>(Wsvu, o, &hs_rT[0][0], accB);
      float pf[8]; upk8(accB, pf);
#pragma unroll
      for (int e = 0; e < TE; e++) pT[o][e] = pf[e];
    }
    __syncthreads();
    float qa[8], qb[8];
    upk8(accA, qa); upk8(accB, qb);
    if (tid < 64) {
#pragma unroll
      for (int e = 0; e < TE; e++) {
        int n = n0 + e;
        if (n >= N) continue;
        float p = pT[o][e];
        out[(size_t)n * 256 + 64 + o * 3 + 0] =
            __ldg(node_v + (size_t)n * 192 + o * 3 + 0) + (qa[e] + p * avx[0][e]) * INVU;
        out[(size_t)n * 256 + 64 + o * 3 + 1] =
            __ldg(node_v + (size_t)n * 192 + o * 3 + 1) + (qb[e] + p * avx[1][e]) * INVU;
      }
    } else {
#pragma unroll
      for (int e = 0; e < TE; e++) {
        int n = n0 + e;
        if (n >= N) continue;
        out[(size_t)n * 256 + 64 + o * 3 + 2] =
            __ldg(node_v + (size_t)n * 192 + o * 3 + 2) + (qa[e] + qb[e] * avx[2][e]) * INVU;
      }
    }
  }
}

extern "C" void kernel_launch(void* const* d_in, const int* in_sizes, int n_in,
                              void* d_out, int out_size) {
  const float* node_s = (const float*)d_in[0];
  const float* node_v = (const float*)d_in[1];
  const float* nas    = (const float*)d_in[2];
  const float* nav    = (const float*)d_in[3];
  const float* eas    = (const float*)d_in[4];
  const float* eav    = (const float*)d_in[5];
  const float* add_f  = (const float*)d_in[6];
  const float* m1Wss  = (const float*)d_in[7];
  const float* m1Wvs  = (const float*)d_in[8];
  const float* m1Wsv  = (const float*)d_in[9];
  const float* m1Wvv  = (const float*)d_in[10];
  const float* m1b    = (const float*)d_in[11];
  const float* m2Wss  = (const float*)d_in[12];
  const float* m2Wvs  = (const float*)d_in[13];
  const float* m2Wsv  = (const float*)d_in[14];
  const float* m2Wvv  = (const float*)d_in[15];
  const float* m2b    = (const float*)d_in[16];
  const float* u0Wss  = (const float*)d_in[17];
  const float* u0Wvs  = (const float*)d_in[18];
  const float* u0Wsv  = (const float*)d_in[19];
  const float* u0Wvv  = (const float*)d_in[20];
  const float* u0b    = (const float*)d_in[21];
  const float* u1Wss  = (const float*)d_in[22];
  const float* u1Wvs  = (const float*)d_in[23];
  const float* u1Wsv  = (const float*)d_in[24];
  const float* u1Wvv  = (const float*)d_in[25];
  const float* u1b    = (const float*)d_in[26];
  const int* senders   = (const int*)d_in[27];
  const int* receivers = (const int*)d_in[28];

  int E = in_sizes[27];
  int N = in_sizes[0] / 64;

  cudaFuncSetAttribute(edge_kernel, cudaFuncAttributeMaxDynamicSharedMemorySize,
                       EDGE_SMEM_BYTES);

  zero_kernel<<<512, 256>>>(N);
  edge_kernel<<<(E + TEE - 1) / TEE, NT, EDGE_SMEM_BYTES>>>(
      node_s, node_v, eas, eav, add_f,
      m1Wss, m1Wvs, m1Wsv, m1Wvv, m1b,
      m2Wss, m2Wvs, m2Wsv, m2Wvv, m2b,
      senders, receivers, E);
  node_kernel<<<(N + TE - 1) / TE, 128>>>(
      node_s, node_v, nas, nav,
      u0Wss, u0Wvs, u0Wsv, u0Wvv, u0b,
      u1Wss, u1Wvs, u1Wsv, u1Wvv, u1b,
      (float*)d_out, N);
}

// round 6
// speedup vs baseline: 1.1453x; 1.0241x over previous
#include <cuda_runtime.h>

#define TE 8
#define NODES_MAX 50000

typedef unsigned long long ull;

__device__ float g_agg_s[(size_t)NODES_MAX * 64];
__device__ float g_agg_v[(size_t)NODES_MAX * 192];

__device__ __forceinline__ ull ffma2(ull a, ull b, ull c) {
  ull d;
  asm("fma.rn.f32x2 %0, %1, %2, %3;" : "=l"(d) : "l"(a), "l"(b), "l"(c));
  return d;
}
__device__ __forceinline__ ull pack2(float x) {
  ull d;
  asm("mov.b64 %0, {%1, %1};" : "=l"(d) : "f"(x));
  return d;
}
__device__ __forceinline__ void upk8(const ull* a, float* f) {
#pragma unroll
  for (int j = 0; j < 4; j++) {
    f[2 * j]     = __int_as_float((int)(unsigned)(a[j] & 0xffffffffull));
    f[2 * j + 1] = __int_as_float((int)(unsigned)(a[j] >> 32));
  }
}
__device__ __forceinline__ float sigm(float x) { return 1.0f / (1.0f + __expf(-x)); }

#define RSQRT3 0.5773502692f
#define INV1   0.0622573010f   // 1/sqrt(258)
#define INV2   0.0883883476f   // 1/sqrt(128)
#define INV0   0.0625f         // 1/sqrt(256)
#define INVU   0.0883883476f   // 1/sqrt(128)

#define ACC4(arrRow, w2, A) do {                                               \
    ulonglong2 _r0 = *reinterpret_cast<const ulonglong2*>(arrRow);             \
    ulonglong2 _r1 = *reinterpret_cast<const ulonglong2*>((arrRow) + 4);       \
    (A)[0] = ffma2(_r0.x, (w2), (A)[0]);                                       \
    (A)[1] = ffma2(_r0.y, (w2), (A)[1]);                                       \
    (A)[2] = ffma2(_r1.x, (w2), (A)[2]);                                       \
    (A)[3] = ffma2(_r1.y, (w2), (A)[3]);                                       \
  } while (0)

// Software-pipelined GEMM: weight block k+8 prefetched while computing block k.
// K must be a multiple of 16 (K=64 or 128 here).
template <int K, int LDW, int RS>
__device__ __forceinline__ void gemmK(const float* __restrict__ W, int o,
                                      const float* __restrict__ row, ull* acc) {
  float wA[8], wB[8];
#pragma unroll
  for (int j = 0; j < 8; j++) wA[j] = __ldg(W + (size_t)j * LDW + o);
#pragma unroll 1
  for (int k0 = 0; k0 < K; k0 += 16) {
#pragma unroll
    for (int j = 0; j < 8; j++) wB[j] = __ldg(W + (size_t)(k0 + 8 + j) * LDW + o);
#pragma unroll
    for (int j = 0; j < 8; j++) {
      ull w2 = pack2(wA[j]);
      ACC4(row + (size_t)(k0 + j) * RS, w2, acc);
    }
    if (k0 + 16 < K) {
#pragma unroll
      for (int j = 0; j < 8; j++) wA[j] = __ldg(W + (size_t)(k0 + 16 + j) * LDW + o);
    }
#pragma unroll
    for (int j = 0; j < 8; j++) {
      ull w2 = pack2(wB[j]);
      ACC4(row + (size_t)(k0 + 8 + j) * RS, w2, acc);
    }
  }
}

// Dual-row variant: same weight feeds two data rows.
template <int K, int LDW, int RS>
__device__ __forceinline__ void gemmK2(const float* __restrict__ W, int o,
                                       const float* __restrict__ row0,
                                       const float* __restrict__ row1,
                                       ull* accA, ull* accB) {
  float wA[8], wB[8];
#pragma unroll
  for (int j = 0; j < 8; j++) wA[j] = __ldg(W + (size_t)j * LDW + o);
#pragma unroll 1
  for (int k0 = 0; k0 < K; k0 += 16) {
#pragma unroll
    for (int j = 0; j < 8; j++) wB[j] = __ldg(W + (size_t)(k0 + 8 + j) * LDW + o);
#pragma unroll
    for (int j = 0; j < 8; j++) {
      ull w2 = pack2(wA[j]);
      ACC4(row0 + (size_t)(k0 + j) * RS, w2, accA);
      ACC4(row1 + (size_t)(k0 + j) * RS, w2, accB);
    }
    if (k0 + 16 < K) {
#pragma unroll
      for (int j = 0; j < 8; j++) wA[j] = __ldg(W + (size_t)(k0 + 16 + j) * LDW + o);
    }
#pragma unroll
    for (int j = 0; j < 8; j++) {
      ull w2 = pack2(wB[j]);
      ACC4(row0 + (size_t)(k0 + 8 + j) * RS, w2, accB == accA ? accA : accA);
      ACC4(row0 + (size_t)(k0 + 8 + j) * RS, w2, accA);
      ACC4(row1 + (size_t)(k0 + 8 + j) * RS, w2, accB);
    }
  }
}

// NOTE: the line above with the ternary was a hazard — define cleanly instead.
#undef GEMMK2_BROKEN

template <int K, int LDW, int RS>
__device__ __forceinline__ void gemmK2v(const float* __restrict__ W, int o,
                                        const float* __restrict__ row0,
                                        const float* __restrict__ row1,
                                        ull* accA, ull* accB) {
  float wA[8], wB[8];
#pragma unroll
  for (int j = 0; j < 8; j++) wA[j] = __ldg(W + (size_t)j * LDW + o);
#pragma unroll 1
  for (int k0 = 0; k0 < K; k0 += 16) {
#pragma unroll
    for (int j = 0; j < 8; j++) wB[j] = __ldg(W + (size_t)(k0 + 8 + j) * LDW + o);
#pragma unroll
    for (int j = 0; j < 8; j++) {
      ull w2 = pack2(wA[j]);
      ACC4(row0 + (size_t)(k0 + j) * RS, w2, accA);
      ACC4(row1 + (size_t)(k0 + j) * RS, w2, accB);
    }
    if (k0 + 16 < K) {
#pragma unroll
      for (int j = 0; j < 8; j++) wA[j] = __ldg(W + (size_t)(k0 + 16 + j) * LDW + o);
    }
#pragma unroll
    for (int j = 0; j < 8; j++) {
      ull w2 = pack2(wB[j]);
      ACC4(row0 + (size_t)(k0 + 8 + j) * RS, w2, accA);
      ACC4(row1 + (size_t)(k0 + 8 + j) * RS, w2, accB);
    }
  }
}

// ---------------------------------------------------------------------------
// Edge kernel: 8 edges/CTA, 128 threads, 5 CTAs/SM (R3 structure).
// ---------------------------------------------------------------------------
__global__ void __launch_bounds__(128, 5) edge_kernel(
    const float* __restrict__ node_s, const float* __restrict__ node_v,
    const float* __restrict__ eas, const float* __restrict__ eav,
    const float* __restrict__ add_feat,
    const float* __restrict__ Wss1, const float* __restrict__ Wvs1,
    const float* __restrict__ Wsv1, const float* __restrict__ Wvv1,
    const float* __restrict__ b1,
    const float* __restrict__ Wss2, const float* __restrict__ Wvs2,
    const float* __restrict__ Wsv2, const float* __restrict__ Wvv2,
    const float* __restrict__ b2,
    const int* __restrict__ senders, const int* __restrict__ receivers,
    int E)
{
  __shared__ __align__(16) float xs_rT[130][TE];
  __shared__ __align__(16) float xs_aT[130][TE];
  __shared__ __align__(16) float d1T[128][TE];
  __shared__ __align__(16) float xvaT[128][3][TE];
  __shared__ __align__(16) float ms_rT[64][TE];
  __shared__ __align__(16) float ms_aT[64][TE];
  __shared__ __align__(16) float gT[64][TE];
  __shared__ __align__(16) float d2T[64][TE];
  __shared__ __align__(16) float mvaT[64][3][TE];
  __shared__ __align__(16) float pT[64][TE];
  __shared__ float asx[TE];
  __shared__ float avx[3][TE];
  __shared__ int sndx[TE], rcvx[TE];

  const int tid = threadIdx.x;
  const int e0 = blockIdx.x * TE;

  if (tid < TE) {
    int ge = e0 + tid;
    bool val = ge < E;
    sndx[tid] = val ? senders[ge] : 0;
    rcvx[tid] = val ? receivers[ge] : -1;
    asx[tid]  = val ? eas[ge] : 0.f;
#pragma unroll
    for (int i = 0; i < 3; i++) avx[i][tid] = val ? eav[ge * 3 + i] : 0.f;
  }
  __syncthreads();

  for (int idx = tid; idx < TE * 130; idx += 128) {
    int e = idx / 130, s = idx - e * 130;
    int r = rcvx[e] < 0 ? 0 : rcvx[e];
    float v;
    if (s < 64)       v = __ldg(node_s + (size_t)sndx[e] * 64 + s);
    else if (s < 128) v = __ldg(node_s + (size_t)r * 64 + (s - 64));
    else {
      int ge = e0 + e;
      v = (ge < E) ? __ldg(add_feat + (size_t)ge * 2 + (s - 128)) : 0.f;
    }
    xs_rT[s][e] = v;
    xs_aT[s][e] = v * asx[e];
  }
  for (int idx = tid; idx < TE * 384; idx += 128) {
    int e = idx / 384, j = idx - e * 384;
    int r = rcvx[e] < 0 ? 0 : rcvx[e];
    float v = (j < 192) ? __ldg(node_v + (size_t)sndx[e] * 192 + j)
                        : __ldg(node_v + (size_t)r * 192 + (j - 192));
    xvaT[j / 3][j % 3][e] = v;
  }
  __syncthreads();

  for (int t = tid; t < TE * 128; t += 128) {
    int v = t >> 3, e = t & 7;
    float r0 = xvaT[v][0][e], r1 = xvaT[v][1][e], r2 = xvaT[v][2][e];
    d1T[v][e] = (r0 * avx[0][e] + r1 * avx[1][e] + r2 * avx[2][e]) * RSQRT3;
    float a = asx[e];
    xvaT[v][0][e] = r0 * a; xvaT[v][1][e] = r1 * a; xvaT[v][2][e] = r2 * a;
  }
  __syncthreads();

  // ---- m1 scalar ----
  {
    const int o = tid;
    ull acc[4] = {0, 0, 0, 0};
    gemmK<128, 128, TE>(Wss1, o, &xs_aT[0][0], acc);
    {
      float w0 = __ldg(Wss1 + (size_t)128 * 128 + o);
      float w1 = __ldg(Wss1 + (size_t)129 * 128 + o);
      ACC4(&xs_aT[128][0], pack2(w0), acc);
      ACC4(&xs_aT[129][0], pack2(w1), acc);
    }
    gemmK<128, 128, TE>(Wvs1, o, &d1T[0][0], acc);
    float sv[8]; upk8(acc, sv);
    float bo = __ldg(b1 + o);
    if (o < 64) {
#pragma unroll
      for (int e = 0; e < TE; e++) {
        float s1 = sv[e] * INV1 + bo;
        float m = s1 * sigm(s1);
        ms_rT[o][e] = m;
        ms_aT[o][e] = m * asx[e];
      }
    } else {
#pragma unroll
      for (int e = 0; e < TE; e++) {
        gT[o - 64][e] = sigm(sv[e] * INV1 + bo);
      }
    }
  }
  __syncthreads();

  // ---- m1 vector ----
  {
    const int o = tid & 63;
    ull accA[4] = {0, 0, 0, 0}, accB[4] = {0, 0, 0, 0};
    if (tid < 64) {
      gemmK2v<128, 64, 3 * TE>(Wvv1, o, &xvaT[0][0][0], &xvaT[0][1][0], accA, accB);
    } else {
      gemmK<128, 64, 3 * TE>(Wvv1, o, &xvaT[0][2][0], accA);
      gemmK<128, 64, TE>(Wsv1, o, &xs_rT[0][0], accB);
      {
        float w0 = __ldg(Wsv1 + (size_t)128 * 64 + o);
        float w1 = __ldg(Wsv1 + (size_t)129 * 64 + o);
        ACC4(&xs_rT[128][0], pack2(w0), accB);
        ACC4(&xs_rT[129][0], pack2(w1), accB);
      }
      float pf[8]; upk8(accB, pf);
#pragma unroll
      for (int e = 0; e < TE; e++) pT[o][e] = pf[e];
    }
    __syncthreads();
    float qa[8], qb[8];
    upk8(accA, qa); upk8(accB, qb);
    if (tid < 64) {
#pragma unroll
      for (int e = 0; e < TE; e++) {
        float gi = gT[o][e] * INV1;
        float p = pT[o][e];
        mvaT[o][0][e] = (qa[e] + p * avx[0][e]) * gi;
        mvaT[o][1][e] = (qb[e] + p * avx[1][e]) * gi;
      }
    } else {
#pragma unroll
      for (int e = 0; e < TE; e++) {
        float gi = gT[o][e] * INV1;
        mvaT[o][2][e] = (qa[e] + qb[e] * avx[2][e]) * gi;
      }
    }
  }
  __syncthreads();

  for (int t = tid; t < TE * 64; t += 128) {
    int v = t >> 3, e = t & 7;
    float r0 = mvaT[v][0][e], r1 = mvaT[v][1][e], r2 = mvaT[v][2][e];
    d2T[v][e] = (r0 * avx[0][e] + r1 * avx[1][e] + r2 * avx[2][e]) * RSQRT3;
    float a = asx[e];
    mvaT[v][0][e] = r0 * a; mvaT[v][1][e] = r1 * a; mvaT[v][2][e] = r2 * a;
  }
  __syncthreads();

  // ---- m2 scalar ----
  {
    const int o = tid;
    ull acc[4] = {0, 0, 0, 0};
    gemmK<64, 128, TE>(Wss2, o, &ms_aT[0][0], acc);
    gemmK<64, 128, TE>(Wvs2, o, &d2T[0][0], acc);
    float sv[8]; upk8(acc, sv);
    float bo = __ldg(b2 + o);
    if (o < 64) {
#pragma unroll
      for (int e = 0; e < TE; e++) {
        float s2 = sv[e] * INV2 + bo;
        float m = s2 * sigm(s2);
        int r = rcvx[e];
        if (r >= 0) atomicAdd(g_agg_s + (size_t)r * 64 + o, m);
      }
    } else {
#pragma unroll
      for (int e = 0; e < TE; e++) {
        gT[o - 64][e] = sigm(sv[e] * INV2 + bo);
      }
    }
  }
  __syncthreads();

  // ---- m2 vector ----
  {
    const int o = tid & 63;
    ull accA[4] = {0, 0, 0, 0}, accB[4] = {0, 0, 0, 0};
    if (tid < 64) {
      gemmK2v<64, 64, 3 * TE>(Wvv2, o, &mvaT[0][0][0], &mvaT[0][1][0], accA, accB);
    } else {
      gemmK<64, 64, 3 * TE>(Wvv2, o, &mvaT[0][2][0], accA);
      gemmK<64, 64, TE>(Wsv2, o, &ms_rT[0][0], accB);
      float pf[8]; upk8(accB, pf);
#pragma unroll
      for (int e = 0; e < TE; e++) pT[o][e] = pf[e];
    }
    __syncthreads();
    float qa[8], qb[8];
    upk8(accA, qa); upk8(accB, qb);
    if (tid < 64) {
#pragma unroll
      for (int e = 0; e < TE; e++) {
        int r = rcvx[e];
        if (r < 0) continue;
        float gi = gT[o][e] * INV2;
        float p = pT[o][e];
        atomicAdd(g_agg_v + (size_t)r * 192 + o * 3 + 0, (qa[e] + p * avx[0][e]) * gi);
        atomicAdd(g_agg_v + (size_t)r * 192 + o * 3 + 1, (qb[e] + p * avx[1][e]) * gi);
      }
    } else {
#pragma unroll
      for (int e = 0; e < TE; e++) {
        int r = rcvx[e];
        if (r < 0) continue;
        float gi = gT[o][e] * INV2;
        atomicAdd(g_agg_v + (size_t)r * 192 + o * 3 + 2, (qa[e] + qb[e] * avx[2][e]) * gi);
      }
    }
  }
}

// ---------------------------------------------------------------------------
// Node kernel (R3 structure + pipelined gemm)
// ---------------------------------------------------------------------------
__global__ void __launch_bounds__(128, 5) node_kernel(
    const float* __restrict__ node_s, const float* __restrict__ node_v,
    const float* __restrict__ nas, const float* __restrict__ nav,
    const float* __restrict__ Wss0, const float* __restrict__ Wvs0,
    const float* __restrict__ Wsv0, const float* __restrict__ Wvv0,
    const float* __restrict__ b0,
    const float* __restrict__ Wssu, const float* __restrict__ Wvsu,
    const float* __restrict__ Wsvu, const float* __restrict__ Wvvu,
    const float* __restrict__ bu,
    float* __restrict__ out, int N)
{
  __shared__ __align__(16) float xs_rT[128][TE];
  __shared__ __align__(16) float xs_aT[128][TE];
  __shared__ __align__(16) float d1T[128][TE];
  __shared__ __align__(16) float xvaT[128][3][TE];
  __shared__ __align__(16) float hs_rT[64][TE];
  __shared__ __align__(16) float hs_aT[64][TE];
  __shared__ __align__(16) float gT[64][TE];
  __shared__ __align__(16) float d2T[64][TE];
  __shared__ __align__(16) float hvaT[64][3][TE];
  __shared__ __align__(16) float pT[64][TE];
  __shared__ float asx[TE], avx[3][TE];

  const int tid = threadIdx.x;
  const int n0 = blockIdx.x * TE;

  if (tid < TE) {
    int n = n0 + tid;
    bool val = n < N;
    asx[tid] = val ? nas[n] : 0.f;
#pragma unroll
    for (int i = 0; i < 3; i++) avx[i][tid] = val ? nav[n * 3 + i] : 0.f;
  }
  __syncthreads();

  for (int idx = tid; idx < TE * 128; idx += 128) {
    int e = idx >> 7, s = idx & 127;
    int n = n0 + e; if (n >= N) n = 0;
    float v = (s < 64) ? __ldg(node_s + (size_t)n * 64 + s)
                       : g_agg_s[(size_t)n * 64 + (s - 64)];
    xs_rT[s][e] = v;
    xs_aT[s][e] = v * asx[e];
  }
  for (int idx = tid; idx < TE * 384; idx += 128) {
    int e = idx / 384, j = idx - e * 384;
    int n = n0 + e; if (n >= N) n = 0;
    float v = (j < 192) ? __ldg(node_v + (size_t)n * 192 + j)
                        : g_agg_v[(size_t)n * 192 + (j - 192)];
    xvaT[j / 3][j % 3][e] = v;
  }
  __syncthreads();

  for (int t = tid; t < TE * 128; t += 128) {
    int v = t >> 3, e = t & 7;
    float r0 = xvaT[v][0][e], r1 = xvaT[v][1][e], r2 = xvaT[v][2][e];
    d1T[v][e] = (r0 * avx[0][e] + r1 * avx[1][e] + r2 * avx[2][e]) * RSQRT3;
    float a = asx[e];
    xvaT[v][0][e] = r0 * a; xvaT[v][1][e] = r1 * a; xvaT[v][2][e] = r2 * a;
  }
  __syncthreads();

  // ---- u0 scalar ----
  {
    const int o = tid;
    ull acc[4] = {0, 0, 0, 0};
    gemmK<128, 128, TE>(Wss0, o, &xs_aT[0][0], acc);
    gemmK<128, 128, TE>(Wvs0, o, &d1T[0][0], acc);
    float sv[8]; upk8(acc, sv);
    float bo = __ldg(b0 + o);
    if (o < 64) {
#pragma unroll
      for (int e = 0; e < TE; e++) {
        float s1 = sv[e] * INV0 + bo;
        float m = s1 * sigm(s1);
        hs_rT[o][e] = m;
        hs_aT[o][e] = m * asx[e];
      }
    } else {
#pragma unroll
      for (int e = 0; e < TE; e++) {
        gT[o - 64][e] = sigm(sv[e] * INV0 + bo);
      }
    }
  }
  __syncthreads();

  // ---- u0 vector ----
  {
    const int o = tid & 63;
    ull accA[4] = {0, 0, 0, 0}, accB[4] = {0, 0, 0, 0};
    if (tid < 64) {
      gemmK2v<128, 64, 3 * TE>(Wvv0, o, &xvaT[0][0][0], &xvaT[0][1][0], accA, accB);
    } else {
      gemmK<128, 64, 3 * TE>(Wvv0, o, &xvaT[0][2][0], accA);
      gemmK<128, 64, TE>(Wsv0, o, &xs_rT[0][0], accB);
      float pf[8]; upk8(accB, pf);
#pragma unroll
      for (int e = 0; e < TE; e++) pT[o][e] = pf[e];
    }
    __syncthreads();
    float qa[8], qb[8];
    upk8(accA, qa); upk8(accB, qb);
    if (tid < 64) {
#pragma unroll
      for (int e = 0; e < TE; e++) {
        float gi = gT[o][e] * INV0;
        float p = pT[o][e];
        hvaT[o][0][e] = (qa[e] + p * avx[0][e]) * gi;
        hvaT[o][1][e] = (qb[e] + p * avx[1][e]) * gi;
      }
    } else {
#pragma unroll
      for (int e = 0; e < TE; e++) {
        float gi = gT[o][e] * INV0;
        hvaT[o][2][e] = (qa[e] + qb[e] * avx[2][e]) * gi;
      }
    }
  }
  __syncthreads();

  for (int t = tid; t < TE * 64; t += 128) {
    int v = t >> 3, e = t & 7;
    float r0 = hvaT[v][0][e], r1 = hvaT[v][1][e], r2 = hvaT[v][2][e];
    d2T[v][e] = (r0 * avx[0][e] + r1 * avx[1][e] + r2 * avx[2][e]) * RSQRT3;
    float a = asx[e];
    hvaT[v][0][e] = r0 * a; hvaT[v][1][e] = r1 * a; hvaT[v][2][e] = r2 * a;
  }
  __syncthreads();

  // ---- u1 scalar + residual ----
  if (tid < 64) {
    const int o = tid;
    ull acc[4] = {0, 0, 0, 0};
    gemmK<64, 64, TE>(Wssu, o, &hs_aT[0][0], acc);
    gemmK<64, 64, TE>(Wvsu, o, &d2T[0][0], acc);
    float sv[8]; upk8(acc, sv);
    float bo = __ldg(bu + o);
#pragma unroll
    for (int e = 0; e < TE; e++) {
      int n = n0 + e;
      if (n < N)
        out[(size_t)n * 256 + o] =
            __ldg(node_s + (size_t)n * 64 + o) + sv[e] * INVU + bo;
    }
  }

  // ---- u1 vector + residual ----
  {
    const int o = tid & 63;
    ull accA[4] = {0, 0, 0, 0}, accB[4] = {0, 0, 0, 0};
    if (tid < 64) {
      gemmK2v<64, 64, 3 * TE>(Wvvu, o, &hvaT[0][0][0], &hvaT[0][1][0], accA, accB);
    } else {
      gemmK<64, 64, 3 * TE>(Wvvu, o, &hvaT[0][2][0], accA);
      gemmK<64, 64, TE>(Wsvu, o, &hs_rT[0][0], accB);
      float pf[8]; upk8(accB, pf);
#pragma unroll
      for (int e = 0; e < TE; e++) pT[o][e] = pf[e];
    }
    __syncthreads();
    float qa[8], qb[8];
    upk8(accA, qa); upk8(accB, qb);
    if (tid < 64) {
#pragma unroll
      for (int e = 0; e < TE; e++) {
        int n = n0 + e;
        if (n >= N) continue;
        float p = pT[o][e];
        out[(size_t)n * 256 + 64 + o * 3 + 0] =
            __ldg(node_v + (size_t)n * 192 + o * 3 + 0) + (qa[e] + p * avx[0][e]) * INVU;
        out[(size_t)n * 256 + 64 + o * 3 + 1] =
            __ldg(node_v + (size_t)n * 192 + o * 3 + 1) + (qb[e] + p * avx[1][e]) * INVU;
      }
    } else {
#pragma unroll
      for (int e = 0; e < TE; e++) {
        int n = n0 + e;
        if (n >= N) continue;
        out[(size_t)n * 256 + 64 + o * 3 + 2] =
            __ldg(node_v + (size_t)n * 192 + o * 3 + 2) + (qa[e] + qb[e] * avx[2][e]) * INVU;
      }
    }
  }
}

extern "C" void kernel_launch(void* const* d_in, const int* in_sizes, int n_in,
                              void* d_out, int out_size) {
  const float* node_s = (const float*)d_in[0];
  const float* node_v = (const float*)d_in[1];
  const float* nas    = (const float*)d_in[2];
  const float* nav    = (const float*)d_in[3];
  const float* eas    = (const float*)d_in[4];
  const float* eav    = (const float*)d_in[5];
  const float* add_f  = (const float*)d_in[6];
  const float* m1Wss  = (const float*)d_in[7];
  const float* m1Wvs  = (const float*)d_in[8];
  const float* m1Wsv  = (const float*)d_in[9];
  const float* m1Wvv  = (const float*)d_in[10];
  const float* m1b    = (const float*)d_in[11];
  const float* m2Wss  = (const float*)d_in[12];
  const float* m2Wvs  = (const float*)d_in[13];
  const float* m2Wsv  = (const float*)d_in[14];
  const float* m2Wvv  = (const float*)d_in[15];
  const float* m2b    = (const float*)d_in[16];
  const float* u0Wss  = (const float*)d_in[17];
  const float* u0Wvs  = (const float*)d_in[18];
  const float* u0Wsv  = (const float*)d_in[19];
  const float* u0Wvv  = (const float*)d_in[20];
  const float* u0b    = (const float*)d_in[21];
  const float* u1Wss  = (const float*)d_in[22];
  const float* u1Wvs  = (const float*)d_in[23];
  const float* u1Wsv  = (const float*)d_in[24];
  const float* u1Wvv  = (const float*)d_in[25];
  const float* u1b    = (const float*)d_in[26];
  const int* senders   = (const int*)d_in[27];
  const int* receivers = (const int*)d_in[28];

  int E = in_sizes[27];
  int N = in_sizes[0] / 64;

  // zero the aggregation buffers via memset (graph-capturable, no allocation)
  void* p_s = nullptr; void* p_v = nullptr;
  cudaGetSymbolAddress(&p_s, g_agg_s);
  cudaGetSymbolAddress(&p_v, g_agg_v);
  cudaMemsetAsync(p_s, 0, (size_t)N * 64 * sizeof(float));
  cudaMemsetAsync(p_v, 0, (size_t)N * 192 * sizeof(float));

  edge_kernel<<<(E + TE - 1) / TE, 128>>>(
      node_s, node_v, eas, eav, add_f,
      m1Wss, m1Wvs, m1Wsv, m1Wvv, m1b,
      m2Wss, m2Wvs, m2Wsv, m2Wvv, m2b,
      senders, receivers, E);
  node_kernel<<<(N + TE - 1) / TE, 128>>>(
      node_s, node_v, nas, nav,
      u0Wss, u0Wvs, u0Wsv, u0Wvv, u0b,
      u1Wss, u1Wvs, u1Wsv, u1Wvv, u1b,
      (float*)d_out, N);
}

// round 7
// speedup vs baseline: 1.3633x; 1.1904x over previous
#include <cuda_runtime.h>

#define TE 8
#define NODES_MAX 50000

typedef unsigned long long ull;

__device__ float g_agg_s[(size_t)NODES_MAX * 64];
__device__ float g_agg_v[(size_t)NODES_MAX * 192];

__device__ __forceinline__ ull ffma2(ull a, ull b, ull c) {
  ull d;
  asm("fma.rn.f32x2 %0, %1, %2, %3;" : "=l"(d) : "l"(a), "l"(b), "l"(c));
  return d;
}
__device__ __forceinline__ ull pack2(float x) {
  ull d;
  asm("mov.b64 %0, {%1, %1};" : "=l"(d) : "f"(x));
  return d;
}
__device__ __forceinline__ void upk8(const ull* a, float* f) {
#pragma unroll
  for (int j = 0; j < 4; j++) {
    f[2 * j]     = __int_as_float((int)(unsigned)(a[j] & 0xffffffffull));
    f[2 * j + 1] = __int_as_float((int)(unsigned)(a[j] >> 32));
  }
}
__device__ __forceinline__ float sigm(float x) { return 1.0f / (1.0f + __expf(-x)); }

#define RSQRT3 0.5773502692f
#define INV1   0.0622573010f   // 1/sqrt(258)
#define INV2   0.0883883476f   // 1/sqrt(128)
#define INV0   0.0625f         // 1/sqrt(256)
#define INVU   0.0883883476f   // 1/sqrt(128)

// Load row once, feed TWO output columns (weights wa, wb).
#define ACC4W2(arrRow, wa, wb, A, B) do {                                      \
    ulonglong2 _r0 = *reinterpret_cast<const ulonglong2*>(arrRow);             \
    ulonglong2 _r1 = *reinterpret_cast<const ulonglong2*>((arrRow) + 4);       \
    (A)[0] = ffma2(_r0.x, (wa), (A)[0]);                                       \
    (B)[0] = ffma2(_r0.x, (wb), (B)[0]);                                       \
    (A)[1] = ffma2(_r0.y, (wa), (A)[1]);                                       \
    (B)[1] = ffma2(_r0.y, (wb), (B)[1]);                                       \
    (A)[2] = ffma2(_r1.x, (wa), (A)[2]);                                       \
    (B)[2] = ffma2(_r1.x, (wb), (B)[2]);                                       \
    (A)[3] = ffma2(_r1.y, (wa), (A)[3]);                                       \
    (B)[3] = ffma2(_r1.y, (wb), (B)[3]);                                       \
  } while (0)

// R=2 GEMM: thread owns output pair (2*o2, 2*o2+1); weights via one LDG.64.
// MLP=8 weight batching; K multiple of 8.
template <int K, int LDW, int RS>
__device__ __forceinline__ void gemmR2(const float* __restrict__ W, int o2,
                                       const float* __restrict__ row,
                                       ull* accA, ull* accB) {
#pragma unroll 1
  for (int k0 = 0; k0 < K; k0 += 8) {
    float2 w[8];
#pragma unroll
    for (int j = 0; j < 8; j++)
      w[j] = __ldg(reinterpret_cast<const float2*>(W + (size_t)(k0 + j) * LDW) + o2);
#pragma unroll
    for (int j = 0; j < 8; j++) {
      ull wa = pack2(w[j].x), wb = pack2(w[j].y);
      ACC4W2(row + (size_t)(k0 + j) * RS, wa, wb, accA, accB);
    }
  }
}

// ---------------------------------------------------------------------------
// Edge kernel: 8 edges/CTA, 128 threads, 5 CTAs/SM, R=2 output tiling.
// ---------------------------------------------------------------------------
__global__ void __launch_bounds__(128, 5) edge_kernel(
    const float* __restrict__ node_s, const float* __restrict__ node_v,
    const float* __restrict__ eas, const float* __restrict__ eav,
    const float* __restrict__ add_feat,
    const float* __restrict__ Wss1, const float* __restrict__ Wvs1,
    const float* __restrict__ Wsv1, const float* __restrict__ Wvv1,
    const float* __restrict__ b1,
    const float* __restrict__ Wss2, const float* __restrict__ Wvs2,
    const float* __restrict__ Wsv2, const float* __restrict__ Wvv2,
    const float* __restrict__ b2,
    const int* __restrict__ senders, const int* __restrict__ receivers,
    int E)
{
  __shared__ __align__(16) float xs_rT[130][TE];
  __shared__ __align__(16) float xs_aT[130][TE];
  __shared__ __align__(16) float d1T[128][TE];
  __shared__ __align__(16) float xvaT[128][3][TE];  // prescaled by a_s after d1
  __shared__ __align__(16) float ms_rT[64][TE];
  __shared__ __align__(16) float ms_aT[64][TE];
  __shared__ __align__(16) float gT[64][TE];
  __shared__ __align__(16) float d2T[64][TE];
  __shared__ __align__(16) float mvaT[64][3][TE];   // also scalar-exchange space
  __shared__ __align__(16) float pT[64][TE];
  __shared__ float asx[TE];
  __shared__ float avx[3][TE];
  __shared__ int sndx[TE], rcvx[TE];

  const int tid = threadIdx.x;
  const int e0 = blockIdx.x * TE;

  if (tid < TE) {
    int ge = e0 + tid;
    bool val = ge < E;
    sndx[tid] = val ? senders[ge] : 0;
    rcvx[tid] = val ? receivers[ge] : -1;
    asx[tid]  = val ? eas[ge] : 0.f;
#pragma unroll
    for (int i = 0; i < 3; i++) avx[i][tid] = val ? eav[ge * 3 + i] : 0.f;
  }
  __syncthreads();

  for (int idx = tid; idx < TE * 130; idx += 128) {
    int e = idx / 130, s = idx - e * 130;
    int r = rcvx[e] < 0 ? 0 : rcvx[e];
    float v;
    if (s < 64)       v = __ldg(node_s + (size_t)sndx[e] * 64 + s);
    else if (s < 128) v = __ldg(node_s + (size_t)r * 64 + (s - 64));
    else {
      int ge = e0 + e;
      v = (ge < E) ? __ldg(add_feat + (size_t)ge * 2 + (s - 128)) : 0.f;
    }
    xs_rT[s][e] = v;
    xs_aT[s][e] = v * asx[e];
  }
  for (int idx = tid; idx < TE * 384; idx += 128) {
    int e = idx / 384, j = idx - e * 384;
    int r = rcvx[e] < 0 ? 0 : rcvx[e];
    float v = (j < 192) ? __ldg(node_v + (size_t)sndx[e] * 192 + j)
                        : __ldg(node_v + (size_t)r * 192 + (j - 192));
    xvaT[j / 3][j % 3][e] = v;
  }
  __syncthreads();

  for (int t = tid; t < TE * 128; t += 128) {
    int v = t >> 3, e = t & 7;
    float r0 = xvaT[v][0][e], r1 = xvaT[v][1][e], r2 = xvaT[v][2][e];
    d1T[v][e] = (r0 * avx[0][e] + r1 * avx[1][e] + r2 * avx[2][e]) * RSQRT3;
    float a = asx[e];
    xvaT[v][0][e] = r0 * a; xvaT[v][1][e] = r1 * a; xvaT[v][2][e] = r2 * a;
  }
  __syncthreads();

  // ---- m1 scalar: split (grp0: xs_a@Wss1, grp1: d1@Wvs1), R=2 each ----
  {
    const int grp = tid >> 6;
    const int o2 = tid & 63;            // outputs 2*o2, 2*o2+1
    float* exch = &mvaT[0][0][0];       // 1536 floats >= 128*8
    ull accA[4] = {0,0,0,0}, accB[4] = {0,0,0,0};
    if (grp == 0) {
      gemmR2<128, 128, TE>(Wss1, o2, &xs_aT[0][0], accA, accB);
      float2 w0 = __ldg(reinterpret_cast<const float2*>(Wss1 + (size_t)128 * 128) + o2);
      float2 w1 = __ldg(reinterpret_cast<const float2*>(Wss1 + (size_t)129 * 128) + o2);
      ACC4W2(&xs_aT[128][0], pack2(w0.x), pack2(w0.y), accA, accB);
      ACC4W2(&xs_aT[129][0], pack2(w1.x), pack2(w1.y), accA, accB);
    } else {
      gemmR2<128, 128, TE>(Wvs1, o2, &d1T[0][0], accA, accB);
      float pa[8], pb[8]; upk8(accA, pa); upk8(accB, pb);
#pragma unroll
      for (int e = 0; e < TE; e++) {
        exch[(2 * o2) * TE + e] = pa[e];
        exch[(2 * o2 + 1) * TE + e] = pb[e];
      }
    }
    __syncthreads();
    if (grp == 0) {
      float pa[8], pb[8]; upk8(accA, pa); upk8(accB, pb);
      int oA = 2 * o2, oB = 2 * o2 + 1;
      float bA = __ldg(b1 + oA), bB = __ldg(b1 + oB);
      if (oA < 64) {
#pragma unroll
        for (int e = 0; e < TE; e++) {
          float s1 = (pa[e] + exch[oA * TE + e]) * INV1 + bA;
          float m = s1 * sigm(s1);
          ms_rT[oA][e] = m; ms_aT[oA][e] = m * asx[e];
          float s2 = (pb[e] + exch[oB * TE + e]) * INV1 + bB;
          float m2 = s2 * sigm(s2);
          ms_rT[oB][e] = m2; ms_aT[oB][e] = m2 * asx[e];
        }
      } else {
#pragma unroll
        for (int e = 0; e < TE; e++) {
          gT[oA - 64][e] = sigm((pa[e] + exch[oA * TE + e]) * INV1 + bA);
          gT[oB - 64][e] = sigm((pb[e] + exch[oB * TE + e]) * INV1 + bB);
        }
      }
    }
  }
  __syncthreads();

  // ---- m1 vector: 4 roles x 32 threads x output pair ----
  {
    const int role = tid >> 5;
    const int o2 = tid & 31;            // outputs 2*o2, 2*o2+1 (of 64)
    ull accA[4] = {0,0,0,0}, accB[4] = {0,0,0,0};
    if (role < 3) {
      gemmR2<128, 64, 3 * TE>(Wvv1, o2, &xvaT[0][role][0], accA, accB);
    } else {
      gemmR2<128, 64, TE>(Wsv1, o2, &xs_rT[0][0], accA, accB);
      float2 w0 = __ldg(reinterpret_cast<const float2*>(Wsv1 + (size_t)128 * 64) + o2);
      float2 w1 = __ldg(reinterpret_cast<const float2*>(Wsv1 + (size_t)129 * 64) + o2);
      ACC4W2(&xs_rT[128][0], pack2(w0.x), pack2(w0.y), accA, accB);
      ACC4W2(&xs_rT[129][0], pack2(w1.x), pack2(w1.y), accA, accB);
      float pa[8], pb[8]; upk8(accA, pa); upk8(accB, pb);
#pragma unroll
      for (int e = 0; e < TE; e++) {
        pT[2 * o2][e] = pa[e];
        pT[2 * o2 + 1][e] = pb[e];
      }
    }
    __syncthreads();
    if (role < 3) {
      float qa[8], qb[8]; upk8(accA, qa); upk8(accB, qb);
      int oA = 2 * o2, oB = 2 * o2 + 1;
#pragma unroll
      for (int e = 0; e < TE; e++) {
        mvaT[oA][role][e] = (qa[e] + pT[oA][e] * avx[role][e]) * gT[oA][e] * INV1;
        mvaT[oB][role][e] = (qb[e] + pT[oB][e] * avx[role][e]) * gT[oB][e] * INV1;
      }
    }
  }
  __syncthreads();

  for (int t = tid; t < TE * 64; t += 128) {
    int v = t >> 3, e = t & 7;
    float r0 = mvaT[v][0][e], r1 = mvaT[v][1][e], r2 = mvaT[v][2][e];
    d2T[v][e] = (r0 * avx[0][e] + r1 * avx[1][e] + r2 * avx[2][e]) * RSQRT3;
    float a = asx[e];
    mvaT[v][0][e] = r0 * a; mvaT[v][1][e] = r1 * a; mvaT[v][2][e] = r2 * a;
  }
  __syncthreads();

  // ---- m2 scalar: split + R=2; exchange via xvaT (retired) ----
  {
    const int grp = tid >> 6;
    const int o2 = tid & 63;
    float* exch = &xvaT[0][0][0];
    ull accA[4] = {0,0,0,0}, accB[4] = {0,0,0,0};
    if (grp == 0) {
      gemmR2<64, 128, TE>(Wss2, o2, &ms_aT[0][0], accA, accB);
    } else {
      gemmR2<64, 128, TE>(Wvs2, o2, &d2T[0][0], accA, accB);
      float pa[8], pb[8]; upk8(accA, pa); upk8(accB, pb);
#pragma unroll
      for (int e = 0; e < TE; e++) {
        exch[(2 * o2) * TE + e] = pa[e];
        exch[(2 * o2 + 1) * TE + e] = pb[e];
      }
    }
    __syncthreads();
    if (grp == 0) {
      float pa[8], pb[8]; upk8(accA, pa); upk8(accB, pb);
      int oA = 2 * o2, oB = 2 * o2 + 1;
      float bA = __ldg(b2 + oA), bB = __ldg(b2 + oB);
      if (oA < 64) {
#pragma unroll
        for (int e = 0; e < TE; e++) {
          int r = rcvx[e];
          if (r < 0) continue;
          float s1 = (pa[e] + exch[oA * TE + e]) * INV2 + bA;
          float s2 = (pb[e] + exch[oB * TE + e]) * INV2 + bB;
          atomicAdd(g_agg_s + (size_t)r * 64 + oA, s1 * sigm(s1));
          atomicAdd(g_agg_s + (size_t)r * 64 + oB, s2 * sigm(s2));
        }
      } else {
#pragma unroll
        for (int e = 0; e < TE; e++) {
          gT[oA - 64][e] = sigm((pa[e] + exch[oA * TE + e]) * INV2 + bA);
          gT[oB - 64][e] = sigm((pb[e] + exch[oB * TE + e]) * INV2 + bB);
        }
      }
    }
  }
  __syncthreads();

  // ---- m2 vector: 4 roles x 32 threads x output pair; atomic scatter ----
  {
    const int role = tid >> 5;
    const int o2 = tid & 31;
    ull accA[4] = {0,0,0,0}, accB[4] = {0,0,0,0};
    if (role < 3) {
      gemmR2<64, 64, 3 * TE>(Wvv2, o2, &mvaT[0][role][0], accA, accB);
    } else {
      gemmR2<64, 64, TE>(Wsv2, o2, &ms_rT[0][0], accA, accB);
      float pa[8], pb[8]; upk8(accA, pa); upk8(accB, pb);
#pragma unroll
      for (int e = 0; e < TE; e++) {
        pT[2 * o2][e] = pa[e];
        pT[2 * o2 + 1][e] = pb[e];
      }
    }
    __syncthreads();
    if (role < 3) {
      float qa[8], qb[8]; upk8(accA, qa); upk8(accB, qb);
      int oA = 2 * o2, oB = 2 * o2 + 1;
#pragma unroll
      for (int e = 0; e < TE; e++) {
        int r = rcvx[e];
        if (r < 0) continue;
        atomicAdd(g_agg_v + (size_t)r * 192 + oA * 3 + role,
                  (qa[e] + pT[oA][e] * avx[role][e]) * gT[oA][e] * INV2);
        atomicAdd(g_agg_v + (size_t)r * 192 + oB * 3 + role,
                  (qb[e] + pT[oB][e] * avx[role][e]) * gT[oB][e] * INV2);
      }
    }
  }
}

// ---------------------------------------------------------------------------
// Node kernel: same R=2 structure for u0/u1.
// ---------------------------------------------------------------------------
__global__ void __launch_bounds__(128, 5) node_kernel(
    const float* __restrict__ node_s, const float* __restrict__ node_v,
    const float* __restrict__ nas, const float* __restrict__ nav,
    const float* __restrict__ Wss0, const float* __restrict__ Wvs0,
    const float* __restrict__ Wsv0, const float* __restrict__ Wvv0,
    const float* __restrict__ b0,
    const float* __restrict__ Wssu, const float* __restrict__ Wvsu,
    const float* __restrict__ Wsvu, const float* __restrict__ Wvvu,
    const float* __restrict__ bu,
    float* __restrict__ out, int N)
{
  __shared__ __align__(16) float xs_rT[128][TE];
  __shared__ __align__(16) float xs_aT[128][TE];
  __shared__ __align__(16) float d1T[128][TE];
  __shared__ __align__(16) float xvaT[128][3][TE];
  __shared__ __align__(16) float hs_rT[64][TE];
  __shared__ __align__(16) float hs_aT[64][TE];
  __shared__ __align__(16) float gT[64][TE];
  __shared__ __align__(16) float d2T[64][TE];
  __shared__ __align__(16) float hvaT[64][3][TE];   // also u0-scalar exchange
  __shared__ __align__(16) float pT[64][TE];
  __shared__ float asx[TE], avx[3][TE];

  const int tid = threadIdx.x;
  const int n0 = blockIdx.x * TE;

  if (tid < TE) {
    int n = n0 + tid;
    bool val = n < N;
    asx[tid] = val ? nas[n] : 0.f;
#pragma unroll
    for (int i = 0; i < 3; i++) avx[i][tid] = val ? nav[n * 3 + i] : 0.f;
  }
  __syncthreads();

  for (int idx = tid; idx < TE * 128; idx += 128) {
    int e = idx >> 7, s = idx & 127;
    int n = n0 + e; if (n >= N) n = 0;
    float v = (s < 64) ? __ldg(node_s + (size_t)n * 64 + s)
                       : g_agg_s[(size_t)n * 64 + (s - 64)];
    xs_rT[s][e] = v;
    xs_aT[s][e] = v * asx[e];
  }
  for (int idx = tid; idx < TE * 384; idx += 128) {
    int e = idx / 384, j = idx - e * 384;
    int n = n0 + e; if (n >= N) n = 0;
    float v = (j < 192) ? __ldg(node_v + (size_t)n * 192 + j)
                        : g_agg_v[(size_t)n * 192 + (j - 192)];
    xvaT[j / 3][j % 3][e] = v;
  }
  __syncthreads();

  for (int t = tid; t < TE * 128; t += 128) {
    int v = t >> 3, e = t & 7;
    float r0 = xvaT[v][0][e], r1 = xvaT[v][1][e], r2 = xvaT[v][2][e];
    d1T[v][e] = (r0 * avx[0][e] + r1 * avx[1][e] + r2 * avx[2][e]) * RSQRT3;
    float a = asx[e];
    xvaT[v][0][e] = r0 * a; xvaT[v][1][e] = r1 * a; xvaT[v][2][e] = r2 * a;
  }
  __syncthreads();

  // ---- u0 scalar: split + R=2; exchange via hvaT ----
  {
    const int grp = tid >> 6;
    const int o2 = tid & 63;
    float* exch = &hvaT[0][0][0];
    ull accA[4] = {0,0,0,0}, accB[4] = {0,0,0,0};
    if (grp == 0) {
      gemmR2<128, 128, TE>(Wss0, o2, &xs_aT[0][0], accA, accB);
    } else {
      gemmR2<128, 128, TE>(Wvs0, o2, &d1T[0][0], accA, accB);
      float pa[8], pb[8]; upk8(accA, pa); upk8(accB, pb);
#pragma unroll
      for (int e = 0; e < TE; e++) {
        exch[(2 * o2) * TE + e] = pa[e];
        exch[(2 * o2 + 1) * TE + e] = pb[e];
      }
    }
    __syncthreads();
    if (grp == 0) {
      float pa[8], pb[8]; upk8(accA, pa); upk8(accB, pb);
      int oA = 2 * o2, oB = 2 * o2 + 1;
      float bA = __ldg(b0 + oA), bB = __ldg(b0 + oB);
      if (oA < 64) {
#pragma unroll
        for (int e = 0; e < TE; e++) {
          float s1 = (pa[e] + exch[oA * TE + e]) * INV0 + bA;
          float m = s1 * sigm(s1);
          hs_rT[oA][e] = m; hs_aT[oA][e] = m * asx[e];
          float s2 = (pb[e] + exch[oB * TE + e]) * INV0 + bB;
          float m2 = s2 * sigm(s2);
          hs_rT[oB][e] = m2; hs_aT[oB][e] = m2 * asx[e];
        }
      } else {
#pragma unroll
        for (int e = 0; e < TE; e++) {
          gT[oA - 64][e] = sigm((pa[e] + exch[oA * TE + e]) * INV0 + bA);
          gT[oB - 64][e] = sigm((pb[e] + exch[oB * TE + e]) * INV0 + bB);
        }
      }
    }
  }
  __syncthreads();

  // ---- u0 vector: 4 roles x 32 threads x pair ----
  {
    const int role = tid >> 5;
    const int o2 = tid & 31;
    ull accA[4] = {0,0,0,0}, accB[4] = {0,0,0,0};
    if (role < 3) {
      gemmR2<128, 64, 3 * TE>(Wvv0, o2, &xvaT[0][role][0], accA, accB);
    } else {
      gemmR2<128, 64, TE>(Wsv0, o2, &xs_rT[0][0], accA, accB);
      float pa[8], pb[8]; upk8(accA, pa); upk8(accB, pb);
#pragma unroll
      for (int e = 0; e < TE; e++) {
        pT[2 * o2][e] = pa[e];
        pT[2 * o2 + 1][e] = pb[e];
      }
    }
    __syncthreads();
    if (role < 3) {
      float qa[8], qb[8]; upk8(accA, qa); upk8(accB, qb);
      int oA = 2 * o2, oB = 2 * o2 + 1;
#pragma unroll
      for (int e = 0; e < TE; e++) {
        hvaT[oA][role][e] = (qa[e] + pT[oA][e] * avx[role][e]) * gT[oA][e] * INV0;
        hvaT[oB][role][e] = (qb[e] + pT[oB][e] * avx[role][e]) * gT[oB][e] * INV0;
      }
    }
  }
  __syncthreads();

  for (int t = tid; t < TE * 64; t += 128) {
    int v = t >> 3, e = t & 7;
    float r0 = hvaT[v][0][e], r1 = hvaT[v][1][e], r2 = hvaT[v][2][e];
    d2T[v][e] = (r0 * avx[0][e] + r1 * avx[1][e] + r2 * avx[2][e]) * RSQRT3;
    float a = asx[e];
    hvaT[v][0][e] = r0 * a; hvaT[v][1][e] = r1 * a; hvaT[v][2][e] = r2 * a;
  }
  __syncthreads();

  // ---- u1 scalar (64 outs): role0 Wssu, role1 Wvsu; exchange via gT ----
  {
    const int role = tid >> 5;
    const int o2 = tid & 31;
    float* exch = &gT[0][0];
    ull accA[4] = {0,0,0,0}, accB[4] = {0,0,0,0};
    if (role == 1) {
      gemmR2<64, 64, TE>(Wvsu, o2, &d2T[0][0], accA, accB);
      float pa[8], pb[8]; upk8(accA, pa); upk8(accB, pb);
#pragma unroll
      for (int e = 0; e < TE; e++) {
        exch[(2 * o2) * TE + e] = pa[e];
        exch[(2 * o2 + 1) * TE + e] = pb[e];
      }
    } else if (role == 0) {
      gemmR2<64, 64, TE>(Wssu, o2, &hs_aT[0][0], accA, accB);
    }
    __syncthreads();
    if (role == 0) {
      float pa[8], pb[8]; upk8(accA, pa); upk8(accB, pb);
      int oA = 2 * o2, oB = 2 * o2 + 1;
      float bA = __ldg(bu + oA), bB = __ldg(bu + oB);
#pragma unroll
      for (int e = 0; e < TE; e++) {
        int n = n0 + e;
        if (n >= N) continue;
        out[(size_t)n * 256 + oA] =
            __ldg(node_s + (size_t)n * 64 + oA) + (pa[e] + exch[oA * TE + e]) * INVU + bA;
        out[(size_t)n * 256 + oB] =
            __ldg(node_s + (size_t)n * 64 + oB) + (pb[e] + exch[oB * TE + e]) * INVU + bB;
      }
    }
  }
  __syncthreads();

  // ---- u1 vector: 4 roles x 32 threads x pair; residual writes ----
  {
    const int role = tid >> 5;
    const int o2 = tid & 31;
    ull accA[4] = {0,0,0,0}, accB[4] = {0,0,0,0};
    if (role < 3) {
      gemmR2<64, 64, 3 * TE>(Wvvu, o2, &hvaT[0][role][0], accA, accB);
    } else {
      gemmR2<64, 64, TE>(Wsvu, o2, &hs_rT[0][0], accA, accB);
      float pa[8], pb[8]; upk8(accA, pa); upk8(accB, pb);
#pragma unroll
      for (int e = 0; e < TE; e++) {
        pT[2 * o2][e] = pa[e];
        pT[2 * o2 + 1][e] = pb[e];
      }
    }
    __syncthreads();
    if (role < 3) {
      float qa[8], qb[8]; upk8(accA, qa); upk8(accB, qb);
      int oA = 2 * o2, oB = 2 * o2 + 1;
#pragma unroll
      for (int e = 0; e < TE; e++) {
        int n = n0 + e;
        if (n >= N) continue;
        out[(size_t)n * 256 + 64 + oA * 3 + role] =
            __ldg(node_v + (size_t)n * 192 + oA * 3 + role) +
            (qa[e] + pT[oA][e] * avx[role][e]) * INVU;
        out[(size_t)n * 256 + 64 + oB * 3 + role] =
            __ldg(node_v + (size_t)n * 192 + oB * 3 + role) +
            (qb[e] + pT[oB][e] * avx[role][e]) * INVU;
      }
    }
  }
}

extern "C" void kernel_launch(void* const* d_in, const int* in_sizes, int n_in,
                              void* d_out, int out_size) {
  const float* node_s = (const float*)d_in[0];
  const float* node_v = (const float*)d_in[1];
  const float* nas    = (const float*)d_in[2];
  const float* nav    = (const float*)d_in[3];
  const float* eas    = (const float*)d_in[4];
  const float* eav    = (const float*)d_in[5];
  const float* add_f  = (const float*)d_in[6];
  const float* m1Wss  = (const float*)d_in[7];
  const float* m1Wvs  = (const float*)d_in[8];
  const float* m1Wsv  = (const float*)d_in[9];
  const float* m1Wvv  = (const float*)d_in[10];
  const float* m1b    = (const float*)d_in[11];
  const float* m2Wss  = (const float*)d_in[12];
  const float* m2Wvs  = (const float*)d_in[13];
  const float* m2Wsv  = (const float*)d_in[14];
  const float* m2Wvv  = (const float*)d_in[15];
  const float* m2b    = (const float*)d_in[16];
  const float* u0Wss  = (const float*)d_in[17];
  const float* u0Wvs  = (const float*)d_in[18];
  const float* u0Wsv  = (const float*)d_in[19];
  const float* u0Wvv  = (const float*)d_in[20];
  const float* u0b    = (const float*)d_in[21];
  const float* u1Wss  = (const float*)d_in[22];
  const float* u1Wvs  = (const float*)d_in[23];
  const float* u1Wsv  = (const float*)d_in[24];
  const float* u1Wvv  = (const float*)d_in[25];
  const float* u1b    = (const float*)d_in[26];
  const int* senders   = (const int*)d_in[27];
  const int* receivers = (const int*)d_in[28];

  int E = in_sizes[27];
  int N = in_sizes[0] / 64;

  void* p_s = nullptr; void* p_v = nullptr;
  cudaGetSymbolAddress(&p_s, g_agg_s);
  cudaGetSymbolAddress(&p_v, g_agg_v);
  cudaMemsetAsync(p_s, 0, (size_t)N * 64 * sizeof(float));
  cudaMemsetAsync(p_v, 0, (size_t)N * 192 * sizeof(float));

  edge_kernel<<<(E + TE - 1) / TE, 128>>>(
      node_s, node_v, eas, eav, add_f,
      m1Wss, m1Wvs, m1Wsv, m1Wvv, m1b,
      m2Wss, m2Wvs, m2Wsv, m2Wvv, m2b,
      senders, receivers, E);
  node_kernel<<<(N + TE - 1) / TE, 128>>>(
      node_s, node_v, nas, nav,
      u0Wss, u0Wvs, u0Wsv, u0Wvv, u0b,
      u1Wss, u1Wvs, u1Wsv, u1Wvv, u1b,
      (float*)d_out, N);
}